// round 4
// baseline (speedup 1.0000x reference)
#include <cuda_runtime.h>
#include <math.h>

#define BB  4
#define NN  1024
#define DM_ 512
#define HH  8
#define CC  3
#define DC_ 16
#define DK_ 64
#define XW  (CC*DC_)   // 48

// ---------------- scratch (device globals; no allocation allowed) ----------
__device__ float g_Q[(size_t)BB*HH*NN*DK_];
__device__ float g_K[(size_t)BB*HH*NN*DK_];
__device__ float g_V[(size_t)BB*HH*NN*DK_];
__device__ float g_AO[(size_t)BB*NN*DM_];
__device__ float g_bias[(size_t)BB*HH*NN*NN];   // worst case; uniform case uses h=0 slice only
__device__ float g_sq[(size_t)BB*NN*CC];
__device__ float g_alpha[HH*CC];
__device__ float g_gcoef[HH*CC];
__device__ int   g_uniform;

// ---------------- coef prep: g = 1/(2 sigma^2), head-uniformity flag -------
__global__ void prep_coef_kernel(const float* __restrict__ alpha,
                                 const float* __restrict__ lsig) {
    if (threadIdx.x == 0 && blockIdx.x == 0) {
        for (int i = 0; i < HH*CC; i++) {
            float s = expf(lsig[i]);
            if (s < 1e-4f) s = 1e-4f;
            g_gcoef[i] = 1.0f / (2.0f * s * s);
            g_alpha[i] = alpha[i];
        }
        int uni = 1;
        for (int h = 1; h < HH; h++)
            for (int c = 0; c < CC; c++)
                if (alpha[h*CC+c] != alpha[c] || lsig[h*CC+c] != lsig[c]) uni = 0;
        g_uniform = uni;
    }
}

// ---------------- per-(b,n,c) squared norms --------------------------------
__global__ void sq_kernel(const float* __restrict__ x) {
    int t = blockIdx.x * blockDim.x + threadIdx.x;
    if (t >= BB*NN*CC) return;
    int c = t % CC; int bn = t / CC;
    const float* p = x + (size_t)bn * XW + c * DC_;
    float s = 0.f;
#pragma unroll
    for (int d = 0; d < DC_; d++) s += p[d] * p[d];
    g_sq[t] = s;
}

// ---------------- generic 64x64 tiled GEMM: out = A @ W^T + bias -----------
// A: [4096,512] row-major; W: [512,512] row-major (out[m,o] = sum_k A[m,k]W[o,k])
// HEADED: scatter o -> (head,dk) into [B,H,N,DK]; else plain [m,o].
template<bool HEADED>
__global__ __launch_bounds__(256)
void gemm_kernel(const float* __restrict__ A, const float* __restrict__ W,
                 const float* __restrict__ bias, float* __restrict__ out,
                 float outScale) {
    __shared__ float As[64][17];
    __shared__ float Bs[64][17];
    const int tid = threadIdx.x;
    const int tx = tid & 15, ty = tid >> 4;
    const int m0 = blockIdx.y * 64, o0 = blockIdx.x * 64;
    const int lrow = tid >> 2, lk = (tid & 3) * 4;

    float acc[4][4] = {};

    for (int kb = 0; kb < 512; kb += 16) {
        __syncthreads();
        float4 av = *(const float4*)(A + (size_t)(m0 + lrow) * 512 + kb + lk);
        float4 wv = *(const float4*)(W + (size_t)(o0 + lrow) * 512 + kb + lk);
        As[lrow][lk+0] = av.x; As[lrow][lk+1] = av.y; As[lrow][lk+2] = av.z; As[lrow][lk+3] = av.w;
        Bs[lrow][lk+0] = wv.x; Bs[lrow][lk+1] = wv.y; Bs[lrow][lk+2] = wv.z; Bs[lrow][lk+3] = wv.w;
        __syncthreads();
#pragma unroll
        for (int kk = 0; kk < 16; kk++) {
            float a[4], b[4];
#pragma unroll
            for (int r = 0; r < 4; r++) a[r] = As[4*ty + r][kk];
#pragma unroll
            for (int c = 0; c < 4; c++) b[c] = Bs[4*tx + c][kk];
#pragma unroll
            for (int r = 0; r < 4; r++)
#pragma unroll
                for (int c = 0; c < 4; c++) acc[r][c] = fmaf(a[r], b[c], acc[r][c]);
        }
    }

#pragma unroll
    for (int r = 0; r < 4; r++) {
        int m = m0 + 4*ty + r;
#pragma unroll
        for (int c = 0; c < 4; c++) {
            int o = o0 + 4*tx + c;
            float v = (acc[r][c] + bias[o]) * outScale;
            if (HEADED) {
                int b2 = m >> 10, n2 = m & 1023;
                int hd = o >> 6, dk = o & 63;
                out[(((size_t)(b2*HH + hd)) * NN + n2) * DK_ + dk] = v;
            } else {
                out[(size_t)m * DM_ + o] = v;
            }
        }
    }
}

// ---------------- geodesic bias matrix -------------------------------------
// bias[b,h,i,j] = sum_c alpha[h,c] * exp(-max(|xi_c - xj_c|^2,0) * g[h,c])
// If coefficients are head-uniform, only h=0 is computed/stored.
__global__ __launch_bounds__(256)
void bias_kernel(const float* __restrict__ x) {
    __shared__ float Xi[64][49];
    __shared__ float Xj[64][49];
    __shared__ float sqi[64][3];
    __shared__ float sqj[64][3];

    const int bh = blockIdx.z;
    const int h2 = bh & (HH-1);
    const int b2 = bh >> 3;
    if (g_uniform && h2 > 0) return;

    const int i0 = blockIdx.y * 64, j0 = blockIdx.x * 64;
    const int tid = threadIdx.x;
    const int tx = tid & 15, ty = tid >> 4;

    const float* xb = x + (size_t)b2 * NN * XW;
#pragma unroll
    for (int t = 0; t < 12; t++) {
        int idx = tid + t * 256;
        int row = idx / XW, col = idx % XW;
        Xi[row][col] = xb[(size_t)(i0 + row) * XW + col];
        Xj[row][col] = xb[(size_t)(j0 + row) * XW + col];
    }
    if (tid < 192) {
        int row = tid / 3, c = tid % 3;
        sqi[row][c] = g_sq[((size_t)b2 * NN + i0 + row) * CC + c];
        sqj[row][c] = g_sq[((size_t)b2 * NN + j0 + row) * CC + c];
    }
    __syncthreads();

    float Acf[CC], Gcf[CC];
#pragma unroll
    for (int c = 0; c < CC; c++) { Acf[c] = g_alpha[h2*CC + c]; Gcf[c] = g_gcoef[h2*CC + c]; }

    float* outp = g_bias + (size_t)(b2*HH + h2) * NN * NN;

#pragma unroll
    for (int r = 0; r < 4; r++) {
        int i = 4*ty + r;
#pragma unroll
        for (int c = 0; c < 4; c++) {
            int j = 4*tx + c;
            float bsum = 0.f;
#pragma unroll
            for (int cm = 0; cm < CC; cm++) {
                float inner = 0.f;
#pragma unroll
                for (int d = 0; d < DC_; d++)
                    inner = fmaf(Xi[i][cm*DC_ + d], Xj[j][cm*DC_ + d], inner);
                float dd = sqi[i][cm] + sqj[j][cm] - 2.f * inner;
                dd = fmaxf(dd, 0.f);
                bsum = fmaf(Acf[cm], __expf(-dd * Gcf[cm]), bsum);
            }
            outp[(size_t)(i0 + i) * NN + (j0 + j)] = bsum;
        }
    }
}

// ---------------- fused flash-style attention ------------------------------
// Block: one (b,h) x 64 query rows. Online softmax over 16 tiles of 64 keys.
__global__ __launch_bounds__(256)
void attn_kernel() {
    extern __shared__ float sm[];
    float* Qs = sm;               // 64*65
    float* Ks = Qs + 64*65;
    float* Vs = Ks + 64*65;
    float* Ps = Vs + 64*65;

    const int bh = blockIdx.y;
    const int b2 = bh >> 3, h2 = bh & 7;
    const int i0 = blockIdx.x * 64;
    const int tid = threadIdx.x;
    const int tx = tid & 15, ty = tid >> 4;
    const int heff = g_uniform ? 0 : h2;

    const float* Qg = g_Q + ((size_t)bh * NN + i0) * DK_;
    const float* Kg = g_K + (size_t)bh * NN * DK_;
    const float* Vg = g_V + (size_t)bh * NN * DK_;
    const float* Bg = g_bias + ((size_t)(b2*HH + heff) * NN + i0) * NN;

#pragma unroll
    for (int t = 0; t < 4; t++) {
        int idx = tid + t * 256;
        int row = idx >> 4, c4 = (idx & 15) * 4;
        float4 v = *(const float4*)(Qg + (size_t)row * DK_ + c4);
        Qs[row*65 + c4 + 0] = v.x; Qs[row*65 + c4 + 1] = v.y;
        Qs[row*65 + c4 + 2] = v.z; Qs[row*65 + c4 + 3] = v.w;
    }

    float m_r[4], l_r[4], O[4][4] = {};
#pragma unroll
    for (int r = 0; r < 4; r++) { m_r[r] = -1e30f; l_r[r] = 0.f; }

    for (int jt = 0; jt < 16; jt++) {
        const int j0 = jt * 64;
        __syncthreads();
#pragma unroll
        for (int t = 0; t < 4; t++) {
            int idx = tid + t * 256;
            int row = idx >> 4, c4 = (idx & 15) * 4;
            float4 kv = *(const float4*)(Kg + (size_t)(j0 + row) * DK_ + c4);
            float4 vv = *(const float4*)(Vg + (size_t)(j0 + row) * DK_ + c4);
            Ks[row*65 + c4 + 0] = kv.x; Ks[row*65 + c4 + 1] = kv.y;
            Ks[row*65 + c4 + 2] = kv.z; Ks[row*65 + c4 + 3] = kv.w;
            Vs[row*65 + c4 + 0] = vv.x; Vs[row*65 + c4 + 1] = vv.y;
            Vs[row*65 + c4 + 2] = vv.z; Vs[row*65 + c4 + 3] = vv.w;
        }
        __syncthreads();

        // S = Q K^T  (Q pre-scaled by 1/sqrt(dk))
        float s[4][4] = {};
#pragma unroll 8
        for (int kk = 0; kk < 64; kk++) {
            float a[4], b[4];
#pragma unroll
            for (int r = 0; r < 4; r++) a[r] = Qs[(4*ty + r)*65 + kk];
#pragma unroll
            for (int c = 0; c < 4; c++) b[c] = Ks[(4*tx + c)*65 + kk];
#pragma unroll
            for (int r = 0; r < 4; r++)
#pragma unroll
                for (int c = 0; c < 4; c++) s[r][c] = fmaf(a[r], b[c], s[r][c]);
        }

        // + geodesic bias
#pragma unroll
        for (int r = 0; r < 4; r++) {
            float4 bv = *(const float4*)(Bg + (size_t)(4*ty + r) * NN + j0 + 4*tx);
            s[r][0] += bv.x; s[r][1] += bv.y; s[r][2] += bv.z; s[r][3] += bv.w;
        }

        // online softmax update
#pragma unroll
        for (int r = 0; r < 4; r++) {
            float mt = fmaxf(fmaxf(s[r][0], s[r][1]), fmaxf(s[r][2], s[r][3]));
#pragma unroll
            for (int off = 1; off < 16; off <<= 1)
                mt = fmaxf(mt, __shfl_xor_sync(0xffffffffu, mt, off));
            float mnew = fmaxf(m_r[r], mt);
            float fac = __expf(m_r[r] - mnew);
            float rs = 0.f;
#pragma unroll
            for (int c = 0; c < 4; c++) { s[r][c] = __expf(s[r][c] - mnew); rs += s[r][c]; }
#pragma unroll
            for (int off = 1; off < 16; off <<= 1)
                rs += __shfl_xor_sync(0xffffffffu, rs, off);
            l_r[r] = l_r[r] * fac + rs;
            m_r[r] = mnew;
#pragma unroll
            for (int c = 0; c < 4; c++) O[r][c] *= fac;
        }

        // stage P, then O += P @ V
#pragma unroll
        for (int r = 0; r < 4; r++)
#pragma unroll
            for (int c = 0; c < 4; c++)
                Ps[(4*ty + r)*65 + 4*tx + c] = s[r][c];
        __syncthreads();

#pragma unroll 8
        for (int j = 0; j < 64; j++) {
            float pr[4], vb[4];
#pragma unroll
            for (int r = 0; r < 4; r++) pr[r] = Ps[(4*ty + r)*65 + j];
#pragma unroll
            for (int c = 0; c < 4; c++) vb[c] = Vs[j*65 + 4*tx + c];
#pragma unroll
            for (int r = 0; r < 4; r++)
#pragma unroll
                for (int c = 0; c < 4; c++) O[r][c] = fmaf(pr[r], vb[c], O[r][c]);
        }
    }

#pragma unroll
    for (int r = 0; r < 4; r++) {
        int n2 = i0 + 4*ty + r;
        float invl = 1.f / l_r[r];
#pragma unroll
        for (int c = 0; c < 4; c++)
            g_AO[((size_t)b2 * NN + n2) * DM_ + h2*DK_ + 4*tx + c] = O[r][c] * invl;
    }
}

// ---------------- launcher -------------------------------------------------
extern "C" void kernel_launch(void* const* d_in, const int* in_sizes, int n_in,
                              void* d_out, int out_size) {
    const float* h    = (const float*)d_in[0];
    const float* x    = (const float*)d_in[1];
    const float* Wq   = (const float*)d_in[2];
    const float* bq   = (const float*)d_in[3];
    const float* Wk   = (const float*)d_in[4];
    const float* bk   = (const float*)d_in[5];
    const float* Wv   = (const float*)d_in[6];
    const float* bv   = (const float*)d_in[7];
    const float* Wo   = (const float*)d_in[8];
    const float* bo   = (const float*)d_in[9];
    const float* alpha= (const float*)d_in[10];
    const float* lsig = (const float*)d_in[11];
    float* out = (float*)d_out;

    void *pQ, *pK, *pV, *pAO;
    cudaGetSymbolAddress(&pQ,  g_Q);
    cudaGetSymbolAddress(&pK,  g_K);
    cudaGetSymbolAddress(&pV,  g_V);
    cudaGetSymbolAddress(&pAO, g_AO);

    prep_coef_kernel<<<1, 32>>>(alpha, lsig);
    sq_kernel<<<(BB*NN*CC + 127)/128, 128>>>(x);

    dim3 ggrid(DM_/64, (BB*NN)/64);   // (8, 64)
    gemm_kernel<true><<<ggrid, 256>>>(h, Wq, bq, (float*)pQ, 0.125f);
    gemm_kernel<true><<<ggrid, 256>>>(h, Wk, bk, (float*)pK, 1.0f);
    gemm_kernel<true><<<ggrid, 256>>>(h, Wv, bv, (float*)pV, 1.0f);

    bias_kernel<<<dim3(NN/64, NN/64, BB*HH), 256>>>(x);

    const int SMEM = 4 * 64 * 65 * sizeof(float);  // 66560 B
    cudaFuncSetAttribute(attn_kernel, cudaFuncAttributeMaxDynamicSharedMemorySize, SMEM);
    attn_kernel<<<dim3(NN/64, BB*HH), 256, SMEM>>>();

    gemm_kernel<false><<<ggrid, 256>>>((const float*)pAO, Wo, bo, out, 1.0f);
}

// round 8
// speedup vs baseline: 4.2981x; 4.2981x over previous
#include <cuda_runtime.h>
#include <cuda_fp16.h>
#include <math.h>
#include <stdint.h>

#define BB  4
#define NN  1024
#define DM_ 512
#define HH  8
#define CC  3
#define DC_ 16
#define DK_ 64
#define XW  (CC*DC_)

// ---------------- device scratch (16B-aligned for vector ld/st) ------------
__device__ __align__(16) __half g_h16[(size_t)BB*NN*DM_];
__device__ __align__(16) __half g_Wq16[DM_*DM_];
__device__ __align__(16) __half g_Wk16[DM_*DM_];
__device__ __align__(16) __half g_Wv16[DM_*DM_];
__device__ __align__(16) __half g_Wo16[DM_*DM_];
__device__ __align__(16) __half g_Q16[(size_t)BB*HH*NN*DK_];
__device__ __align__(16) __half g_K16[(size_t)BB*HH*NN*DK_];
__device__ __align__(16) __half g_V16[(size_t)BB*HH*NN*DK_];
__device__ __align__(16) __half g_AO16[(size_t)BB*NN*DM_];
__device__ __align__(16) float  g_bias[(size_t)BB*HH*NN*NN];
__device__ __align__(16) float  g_sq[BB*NN*CC];
__device__ __align__(16) float  g_alpha[HH*CC];
__device__ __align__(16) float  g_gcoef[HH*CC];
__device__ int    g_uniform;

// ---------------- helpers ----------------
__device__ __forceinline__ uint32_t smem_u32(const void* p) {
    uint32_t a;
    asm("{ .reg .u64 t; cvta.to.shared.u64 t, %1; cvt.u32.u64 %0, t; }" : "=r"(a) : "l"(p));
    return a;
}
__device__ __forceinline__ uint32_t swz(uint32_t o) { return o ^ ((o >> 3) & 0x70); }

__device__ __forceinline__ void mma16816(float* d, const uint32_t* a, const uint32_t* b) {
    asm volatile("mma.sync.aligned.m16n8k16.row.col.f32.f16.f16.f32 "
        "{%0,%1,%2,%3}, {%4,%5,%6,%7}, {%8,%9}, {%0,%1,%2,%3};"
        : "+f"(d[0]), "+f"(d[1]), "+f"(d[2]), "+f"(d[3])
        : "r"(a[0]), "r"(a[1]), "r"(a[2]), "r"(a[3]), "r"(b[0]), "r"(b[1]));
}
__device__ __forceinline__ void ldm_x4(uint32_t* r, uint32_t addr) {
    asm volatile("ldmatrix.sync.aligned.m8n8.x4.shared.b16 {%0,%1,%2,%3}, [%4];"
        : "=r"(r[0]), "=r"(r[1]), "=r"(r[2]), "=r"(r[3]) : "r"(addr));
}
__device__ __forceinline__ void ldm_x4_t(uint32_t* r, uint32_t addr) {
    asm volatile("ldmatrix.sync.aligned.m8n8.x4.trans.shared.b16 {%0,%1,%2,%3}, [%4];"
        : "=r"(r[0]), "=r"(r[1]), "=r"(r[2]), "=r"(r[3]) : "r"(addr));
}

// ---------------- small prep kernels ----------------
__global__ void prep_coef_kernel(const float* __restrict__ alpha, const float* __restrict__ lsig) {
    if (threadIdx.x == 0 && blockIdx.x == 0) {
        for (int i = 0; i < HH*CC; i++) {
            float s = expf(lsig[i]);
            if (s < 1e-4f) s = 1e-4f;
            g_gcoef[i] = 1.0f / (2.0f * s * s);
            g_alpha[i] = alpha[i];
        }
        int uni = 1;
        for (int h = 1; h < HH; h++)
            for (int c = 0; c < CC; c++)
                if (alpha[h*CC+c] != alpha[c] || lsig[h*CC+c] != lsig[c]) uni = 0;
        g_uniform = uni;
    }
}

__global__ void sq_kernel(const float* __restrict__ x) {
    int t = blockIdx.x * blockDim.x + threadIdx.x;
    if (t >= BB*NN*CC) return;
    int c = t % CC; int bn = t / CC;
    const float* p = x + (size_t)bn * XW + c * DC_;
    float s = 0.f;
#pragma unroll
    for (int d = 0; d < DC_; d++) s += p[d] * p[d];
    g_sq[t] = s;
}

__global__ void convert_kernel(const float* __restrict__ h,
                               const float* __restrict__ wq, const float* __restrict__ wk,
                               const float* __restrict__ wv, const float* __restrict__ wo) {
    int i = blockIdx.x * blockDim.x + threadIdx.x;
    if (i < BB*NN*DM_) g_h16[i] = __float2half_rn(h[i]);
    if (i < DM_*DM_) {
        g_Wq16[i] = __float2half_rn(wq[i]);
        g_Wk16[i] = __float2half_rn(wk[i]);
        g_Wv16[i] = __float2half_rn(wv[i]);
        g_Wo16[i] = __float2half_rn(wo[i]);
    }
}

// ---------------- geodesic bias (fp32) ----------------
__global__ __launch_bounds__(256)
void bias_kernel(const float* __restrict__ x) {
    __shared__ float Xi[64][49];
    __shared__ float Xj[64][49];
    __shared__ float sqi[64][3];
    __shared__ float sqj[64][3];

    const int bh = blockIdx.z;
    const int h2 = bh & (HH-1);
    const int b2 = bh >> 3;
    if (g_uniform && h2 > 0) return;

    const int i0 = blockIdx.y * 64, j0 = blockIdx.x * 64;
    const int tid = threadIdx.x;
    const int tx = tid & 15, ty = tid >> 4;

    const float* xb = x + (size_t)b2 * NN * XW;
#pragma unroll
    for (int t = 0; t < 12; t++) {
        int idx = tid + t * 256;
        int row = idx / XW, col = idx % XW;
        Xi[row][col] = xb[(size_t)(i0 + row) * XW + col];
        Xj[row][col] = xb[(size_t)(j0 + row) * XW + col];
    }
    if (tid < 192) {
        int row = tid / 3, c = tid % 3;
        sqi[row][c] = g_sq[((size_t)b2 * NN + i0 + row) * CC + c];
        sqj[row][c] = g_sq[((size_t)b2 * NN + j0 + row) * CC + c];
    }
    __syncthreads();

    float Acf[CC], Gcf[CC];
#pragma unroll
    for (int c = 0; c < CC; c++) { Acf[c] = g_alpha[h2*CC + c]; Gcf[c] = g_gcoef[h2*CC + c]; }

    float* outp = g_bias + (size_t)(b2*HH + h2) * NN * NN;

#pragma unroll
    for (int r = 0; r < 4; r++) {
        int i = 4*ty + r;
#pragma unroll
        for (int c = 0; c < 4; c++) {
            int j = 4*tx + c;
            float bsum = 0.f;
#pragma unroll
            for (int cm = 0; cm < CC; cm++) {
                float inner = 0.f;
#pragma unroll
                for (int d = 0; d < DC_; d++)
                    inner = fmaf(Xi[i][cm*DC_ + d], Xj[j][cm*DC_ + d], inner);
                float dd = fmaxf(sqi[i][cm] + sqj[j][cm] - 2.f * inner, 0.f);
                bsum = fmaf(Acf[cm], __expf(-dd * Gcf[cm]), bsum);
            }
            outp[(size_t)(i0 + i) * NN + (j0 + j)] = bsum;
        }
    }
}

// ---------------- HMMA GEMM mainloop (128x128 block, K=512) ----------------
// smem double buffer: buf b at b*32768: A tile [128][64]h swz @0, B tile @16384
#define GSMEM 65536

__device__ __forceinline__ void hmma_mainloop(const __half* __restrict__ A,
                                              const __half* __restrict__ W,
                                              char* smem, int m0, int o0,
                                              float acc[4][4][4]) {
    const int tid = threadIdx.x;
    const int lane = tid & 31, wid = tid >> 5;
    const int wm = wid >> 2, wn = wid & 3;
    const uint32_t sb = smem_u32(smem);

    uint4 pa[4], pb[4];
#pragma unroll
    for (int i = 0; i < 4; i++) {
        int idx = tid + i * 256, row = idx >> 3, seg = idx & 7;
        pa[i] = *(const uint4*)(A + (size_t)(m0 + row) * DM_ + seg * 8);
        pb[i] = *(const uint4*)(W + (size_t)(o0 + row) * DM_ + seg * 8);
    }
#pragma unroll
    for (int i = 0; i < 4; i++) {
        int idx = tid + i * 256, row = idx >> 3, seg = idx & 7;
        uint32_t sw = swz((uint32_t)(row * 128 + seg * 16));
        *(uint4*)(smem + sw) = pa[i];
        *(uint4*)(smem + 16384 + sw) = pb[i];
    }
    __syncthreads();

    for (int kt = 0; kt < 8; kt++) {
        const int buf = kt & 1;
        if (kt < 7) {
#pragma unroll
            for (int i = 0; i < 4; i++) {
                int idx = tid + i * 256, row = idx >> 3, seg = idx & 7;
                pa[i] = *(const uint4*)(A + (size_t)(m0 + row) * DM_ + (kt+1)*64 + seg * 8);
                pb[i] = *(const uint4*)(W + (size_t)(o0 + row) * DM_ + (kt+1)*64 + seg * 8);
            }
        }
        const uint32_t abase = sb + buf * 32768;
        const uint32_t bbase = abase + 16384;
#pragma unroll
        for (int ks = 0; ks < 4; ks++) {
            uint32_t af[4][4];
#pragma unroll
            for (int mt = 0; mt < 4; mt++)
                ldm_x4(af[mt], abase + swz((uint32_t)((wm*64 + mt*16 + (lane & 15)) * 128
                                                      + ks*32 + ((lane >> 4) & 1) * 16)));
#pragma unroll
            for (int np = 0; np < 2; np++) {
                uint32_t bf[4];
                ldm_x4(bf, bbase + swz((uint32_t)((wn*32 + np*16 + (lane & 7) + ((lane >> 4) & 1)*8) * 128
                                                  + ks*32 + ((lane >> 3) & 1) * 16)));
#pragma unroll
                for (int mt = 0; mt < 4; mt++) {
                    mma16816(acc[mt][np*2],     af[mt], bf);
                    mma16816(acc[mt][np*2 + 1], af[mt], bf + 2);
                }
            }
        }
        if (kt < 7) {
            const int nbuf = (kt + 1) & 1;
#pragma unroll
            for (int i = 0; i < 4; i++) {
                int idx = tid + i * 256, row = idx >> 3, seg = idx & 7;
                uint32_t sw = swz((uint32_t)(row * 128 + seg * 16));
                *(uint4*)(smem + nbuf * 32768 + sw) = pa[i];
                *(uint4*)(smem + nbuf * 32768 + 16384 + sw) = pb[i];
            }
            __syncthreads();
        }
    }
}

__global__ __launch_bounds__(256)
void qkv_gemm(const float* __restrict__ bq, const float* __restrict__ bk, const float* __restrict__ bv) {
    extern __shared__ char smem[];
    const int z = blockIdx.z;
    const __half* W = (z == 0) ? g_Wq16 : ((z == 1) ? g_Wk16 : g_Wv16);
    const float* bias = (z == 0) ? bq : ((z == 1) ? bk : bv);
    __half* OUT = (z == 0) ? g_Q16 : ((z == 1) ? g_K16 : g_V16);
    const float scale = (z == 0) ? 0.125f : 1.0f;
    const int m0 = blockIdx.y * 128, o0 = blockIdx.x * 128;

    float acc[4][4][4] = {};
    hmma_mainloop(g_h16, W, smem, m0, o0, acc);

    const int lane = threadIdx.x & 31, wid = threadIdx.x >> 5;
    const int wm = wid >> 2, wn = wid & 3;
    const int g = lane >> 2, t2 = (lane & 3) * 2;
#pragma unroll
    for (int mt = 0; mt < 4; mt++) {
#pragma unroll
        for (int nt = 0; nt < 4; nt++) {
            int o = o0 + wn*32 + nt*8 + t2;
            int hd = o >> 6, dk0 = o & 63;
            float b0 = bias[o], b1 = bias[o + 1];
#pragma unroll
            for (int half = 0; half < 2; half++) {
                int m = m0 + wm*64 + mt*16 + g + half*8;
                int b2 = m >> 10, n2 = m & 1023;
                float v0 = (acc[mt][nt][half*2]     + b0) * scale;
                float v1 = (acc[mt][nt][half*2 + 1] + b1) * scale;
                __half2 hh = __floats2half2_rn(v0, v1);
                *(__half2*)(OUT + (((size_t)(b2*HH + hd)) * NN + n2) * DK_ + dk0) = hh;
            }
        }
    }
}

__global__ __launch_bounds__(256)
void out_gemm(const float* __restrict__ bo, float* __restrict__ out) {
    extern __shared__ char smem[];
    const int m0 = blockIdx.y * 128, o0 = blockIdx.x * 128;

    float acc[4][4][4] = {};
    hmma_mainloop(g_AO16, g_Wo16, smem, m0, o0, acc);

    const int lane = threadIdx.x & 31, wid = threadIdx.x >> 5;
    const int wm = wid >> 2, wn = wid & 3;
    const int g = lane >> 2, t2 = (lane & 3) * 2;
#pragma unroll
    for (int mt = 0; mt < 4; mt++) {
#pragma unroll
        for (int nt = 0; nt < 4; nt++) {
            int o = o0 + wn*32 + nt*8 + t2;
            float b0 = bo[o], b1 = bo[o + 1];
#pragma unroll
            for (int half = 0; half < 2; half++) {
                int m = m0 + wm*64 + mt*16 + g + half*8;
                float* dst = out + (size_t)m * DM_ + o;
                dst[0] = acc[mt][nt][half*2]     + b0;
                dst[1] = acc[mt][nt][half*2 + 1] + b1;
            }
        }
    }
}

// ---------------- HMMA flash attention ----------------
// Block = (b,h) x 128 Q rows, 256 thr / 8 warps; warp w owns Q rows 16w..16w+15.
// smem: Q @0 (16KB), K @16384 (16KB), V @32768 (16KB)  -> 48KB
#define ASMEM 49152

__global__ __launch_bounds__(256, 1)
void attn_hmma() {
    extern __shared__ char smem[];
    const uint32_t sb = smem_u32(smem);
    const int tid = threadIdx.x;
    const int lane = tid & 31, w = tid >> 5;
    const int g = lane >> 2, t2 = (lane & 3) * 2;

    const int bh = blockIdx.y;
    const int b2 = bh >> 3, h2 = bh & 7;
    const int i0 = blockIdx.x * 128;
    const int heff = g_uniform ? 0 : h2;

    const uint32_t QOFF = 0, KOFF = 16384, VOFF = 32768;

    // load Q tile [128][64] swizzled — one 16B segment per store
    const __half* Qg = g_Q16 + ((size_t)bh * NN + i0) * DK_;
#pragma unroll
    for (int i = 0; i < 4; i++) {
        int idx = tid + i * 256, row = idx >> 3, seg = idx & 7;
        uint32_t sw = swz((uint32_t)(row * 128 + seg * 16));
        *(uint4*)(smem + QOFF + sw) = *(const uint4*)(Qg + (size_t)row * DK_ + seg * 8);
    }
    __syncthreads();

    // Q fragments register-resident: 4 k16 steps
    uint32_t qa[4][4];
#pragma unroll
    for (int ks = 0; ks < 4; ks++)
        ldm_x4(qa[ks], sb + QOFF + swz((uint32_t)((w*16 + (lane & 15)) * 128
                                                  + ks*32 + ((lane >> 4) & 1) * 16)));
    __syncthreads();

    float m1 = -1e30f, m2 = -1e30f, l1 = 0.f, l2 = 0.f;
    float o_[8][4] = {};

    const __half* Kb = g_K16 + (size_t)bh * NN * DK_;
    const __half* Vb = g_V16 + (size_t)bh * NN * DK_;
    const float* Bg = g_bias + ((size_t)(b2*HH + heff) * NN + i0) * NN;

    for (int jt = 0; jt < 8; jt++) {
        const int j0 = jt * 128;
        __syncthreads();
#pragma unroll
        for (int i = 0; i < 4; i++) {
            int idx = tid + i * 256, row = idx >> 3, seg = idx & 7;
            uint32_t sw = swz((uint32_t)(row * 128 + seg * 16));
            *(uint4*)(smem + KOFF + sw) = *(const uint4*)(Kb + (size_t)(j0 + row) * DK_ + seg * 8);
            *(uint4*)(smem + VOFF + sw) = *(const uint4*)(Vb + (size_t)(j0 + row) * DK_ + seg * 8);
        }
        __syncthreads();

        // S = Q @ K^T : 16 n8 tiles
        float sf[16][4] = {};
#pragma unroll
        for (int np = 0; np < 8; np++) {
#pragma unroll
            for (int ks = 0; ks < 4; ks++) {
                uint32_t bf[4];
                ldm_x4(bf, sb + KOFF + swz((uint32_t)((np*16 + (lane & 7) + ((lane >> 4) & 1)*8) * 128
                                                      + ks*32 + ((lane >> 3) & 1) * 16)));
                mma16816(sf[np*2],     qa[ks], bf);
                mma16816(sf[np*2 + 1], qa[ks], bf + 2);
            }
        }

        // + bias (fp32, direct from L2)
        const float* bp1 = Bg + (size_t)(16*w + g) * NN + j0 + t2;
        const float* bp2 = bp1 + 8 * NN;
#pragma unroll
        for (int nt = 0; nt < 16; nt++) {
            float2 bv1 = *(const float2*)(bp1 + nt*8);
            float2 bv2 = *(const float2*)(bp2 + nt*8);
            sf[nt][0] += bv1.x; sf[nt][1] += bv1.y;
            sf[nt][2] += bv2.x; sf[nt][3] += bv2.y;
        }

        // warp-local online softmax (rows g and g+8 of this warp's slab)
        float mx1 = sf[0][0], mx2 = sf[0][2];
#pragma unroll
        for (int nt = 0; nt < 16; nt++) {
            mx1 = fmaxf(mx1, fmaxf(sf[nt][0], sf[nt][1]));
            mx2 = fmaxf(mx2, fmaxf(sf[nt][2], sf[nt][3]));
        }
        mx1 = fmaxf(mx1, __shfl_xor_sync(0xffffffffu, mx1, 1));
        mx1 = fmaxf(mx1, __shfl_xor_sync(0xffffffffu, mx1, 2));
        mx2 = fmaxf(mx2, __shfl_xor_sync(0xffffffffu, mx2, 1));
        mx2 = fmaxf(mx2, __shfl_xor_sync(0xffffffffu, mx2, 2));

        float n1 = fmaxf(m1, mx1), n2 = fmaxf(m2, mx2);
        float f1 = __expf(m1 - n1), f2 = __expf(m2 - n2);
        float rs1 = 0.f, rs2 = 0.f;
#pragma unroll
        for (int nt = 0; nt < 16; nt++) {
            sf[nt][0] = __expf(sf[nt][0] - n1);
            sf[nt][1] = __expf(sf[nt][1] - n1);
            sf[nt][2] = __expf(sf[nt][2] - n2);
            sf[nt][3] = __expf(sf[nt][3] - n2);
            rs1 += sf[nt][0] + sf[nt][1];
            rs2 += sf[nt][2] + sf[nt][3];
        }
        rs1 += __shfl_xor_sync(0xffffffffu, rs1, 1);
        rs1 += __shfl_xor_sync(0xffffffffu, rs1, 2);
        rs2 += __shfl_xor_sync(0xffffffffu, rs2, 1);
        rs2 += __shfl_xor_sync(0xffffffffu, rs2, 2);
        l1 = l1 * f1 + rs1;  m1 = n1;
        l2 = l2 * f2 + rs2;  m2 = n2;

#pragma unroll
        for (int dt = 0; dt < 8; dt++) {
            o_[dt][0] *= f1; o_[dt][1] *= f1;
            o_[dt][2] *= f2; o_[dt][3] *= f2;
        }

        // O += P @ V : k over j (8 k16 chunks), n over d (8 n8 tiles)
#pragma unroll
        for (int kk = 0; kk < 8; kk++) {
            uint32_t pa[4];
            {
                __half2 h0 = __floats2half2_rn(sf[2*kk][0],   sf[2*kk][1]);
                __half2 h1 = __floats2half2_rn(sf[2*kk][2],   sf[2*kk][3]);
                __half2 h2_ = __floats2half2_rn(sf[2*kk+1][0], sf[2*kk+1][1]);
                __half2 h3 = __floats2half2_rn(sf[2*kk+1][2], sf[2*kk+1][3]);
                pa[0] = *(uint32_t*)&h0; pa[1] = *(uint32_t*)&h1;
                pa[2] = *(uint32_t*)&h2_; pa[3] = *(uint32_t*)&h3;
            }
#pragma unroll
            for (int dp = 0; dp < 4; dp++) {
                uint32_t bf[4];
                ldm_x4_t(bf, sb + VOFF + swz((uint32_t)((kk*16 + (lane & 7) + ((lane >> 3) & 1)*8) * 128
                                                        + dp*32 + ((lane >> 4) & 1) * 16)));
                mma16816(o_[dp*2],     pa, bf);
                mma16816(o_[dp*2 + 1], pa, bf + 2);
            }
        }
    }

    // epilogue
    float i1 = 1.0f / l1, i2 = 1.0f / l2;
    __half* dst1 = g_AO16 + ((size_t)b2 * NN + i0 + 16*w + g)     * DM_ + h2*DK_ + t2;
    __half* dst2 = g_AO16 + ((size_t)b2 * NN + i0 + 16*w + g + 8) * DM_ + h2*DK_ + t2;
#pragma unroll
    for (int dt = 0; dt < 8; dt++) {
        *(__half2*)(dst1 + dt*8) = __floats2half2_rn(o_[dt][0] * i1, o_[dt][1] * i1);
        *(__half2*)(dst2 + dt*8) = __floats2half2_rn(o_[dt][2] * i2, o_[dt][3] * i2);
    }
}

// ---------------- launcher ----------------
extern "C" void kernel_launch(void* const* d_in, const int* in_sizes, int n_in,
                              void* d_out, int out_size) {
    const float* h    = (const float*)d_in[0];
    const float* x    = (const float*)d_in[1];
    const float* Wq   = (const float*)d_in[2];
    const float* bq   = (const float*)d_in[3];
    const float* Wk   = (const float*)d_in[4];
    const float* bk   = (const float*)d_in[5];
    const float* Wv   = (const float*)d_in[6];
    const float* bv   = (const float*)d_in[7];
    const float* Wo   = (const float*)d_in[8];
    const float* bo   = (const float*)d_in[9];
    const float* alpha= (const float*)d_in[10];
    const float* lsig = (const float*)d_in[11];
    float* out = (float*)d_out;

    cudaFuncSetAttribute(qkv_gemm, cudaFuncAttributeMaxDynamicSharedMemorySize, GSMEM);
    cudaFuncSetAttribute(out_gemm, cudaFuncAttributeMaxDynamicSharedMemorySize, GSMEM);
    cudaFuncSetAttribute(attn_hmma, cudaFuncAttributeMaxDynamicSharedMemorySize, ASMEM);

    prep_coef_kernel<<<1, 32>>>(alpha, lsig);
    sq_kernel<<<(BB*NN*CC + 127)/128, 128>>>(x);
    convert_kernel<<<(BB*NN*DM_ + 255)/256, 256>>>(h, Wq, Wk, Wv, Wo);

    qkv_gemm<<<dim3(DM_/128, (BB*NN)/128, 3), 256, GSMEM>>>(bq, bk, bv);

    bias_kernel<<<dim3(NN/64, NN/64, BB*HH), 256>>>(x);

    attn_hmma<<<dim3(NN/128, BB*HH), 256, ASMEM>>>();

    out_gemm<<<dim3(DM_/128, (BB*NN)/128), 256, GSMEM>>>(bo, out);
}

// round 9
// speedup vs baseline: 4.9897x; 1.1609x over previous
#include <cuda_runtime.h>
#include <cuda_fp16.h>
#include <math.h>
#include <stdint.h>

#define BB  4
#define NN  1024
#define DM_ 512
#define HH  8
#define CC  3
#define DC_ 16
#define DK_ 64
#define XW  (CC*DC_)

// ---------------- device scratch (16B-aligned for vector ld/st) ------------
__device__ __align__(16) __half g_h16[(size_t)BB*NN*DM_];
__device__ __align__(16) __half g_Wq16[DM_*DM_];
__device__ __align__(16) __half g_Wk16[DM_*DM_];
__device__ __align__(16) __half g_Wv16[DM_*DM_];
__device__ __align__(16) __half g_Wo16[DM_*DM_];
__device__ __align__(16) __half g_Q16[(size_t)BB*HH*NN*DK_];
__device__ __align__(16) __half g_K16[(size_t)BB*HH*NN*DK_];
__device__ __align__(16) __half g_V16[(size_t)BB*HH*NN*DK_];
__device__ __align__(16) __half g_AO16[(size_t)BB*NN*DM_];
__device__ __align__(16) float  g_bias[(size_t)BB*HH*NN*NN];
__device__ __align__(16) float  g_sq[BB*NN*CC];
__device__ __align__(16) float  g_alpha[HH*CC];
__device__ __align__(16) float  g_gcoef[HH*CC];
__device__ int    g_uniform;

// ---------------- helpers ----------------
__device__ __forceinline__ uint32_t smem_u32(const void* p) {
    uint32_t a;
    asm("{ .reg .u64 t; cvta.to.shared.u64 t, %1; cvt.u32.u64 %0, t; }" : "=r"(a) : "l"(p));
    return a;
}
__device__ __forceinline__ uint32_t swz(uint32_t o) { return o ^ ((o >> 3) & 0x70); }

__device__ __forceinline__ void mma16816(float* d, const uint32_t* a, const uint32_t* b) {
    asm volatile("mma.sync.aligned.m16n8k16.row.col.f32.f16.f16.f32 "
        "{%0,%1,%2,%3}, {%4,%5,%6,%7}, {%8,%9}, {%0,%1,%2,%3};"
        : "+f"(d[0]), "+f"(d[1]), "+f"(d[2]), "+f"(d[3])
        : "r"(a[0]), "r"(a[1]), "r"(a[2]), "r"(a[3]), "r"(b[0]), "r"(b[1]));
}
__device__ __forceinline__ void ldm_x4(uint32_t* r, uint32_t addr) {
    asm volatile("ldmatrix.sync.aligned.m8n8.x4.shared.b16 {%0,%1,%2,%3}, [%4];"
        : "=r"(r[0]), "=r"(r[1]), "=r"(r[2]), "=r"(r[3]) : "r"(addr));
}
__device__ __forceinline__ void ldm_x4_t(uint32_t* r, uint32_t addr) {
    asm volatile("ldmatrix.sync.aligned.m8n8.x4.trans.shared.b16 {%0,%1,%2,%3}, [%4];"
        : "=r"(r[0]), "=r"(r[1]), "=r"(r[2]), "=r"(r[3]) : "r"(addr));
}
__device__ __forceinline__ void cp16(uint32_t saddr, const void* gptr) {
    asm volatile("cp.async.cg.shared.global [%0], [%1], 16;" :: "r"(saddr), "l"(gptr));
}
#define CP_COMMIT() asm volatile("cp.async.commit_group;" ::: "memory")
#define CP_WAIT1()  asm volatile("cp.async.wait_group 1;" ::: "memory")

// ---------------- small prep kernels ----------------
__global__ void prep_coef_kernel(const float* __restrict__ alpha, const float* __restrict__ lsig) {
    if (threadIdx.x == 0 && blockIdx.x == 0) {
        for (int i = 0; i < HH*CC; i++) {
            float s = expf(lsig[i]);
            if (s < 1e-4f) s = 1e-4f;
            g_gcoef[i] = 1.0f / (2.0f * s * s);
            g_alpha[i] = alpha[i];
        }
        int uni = 1;
        for (int h = 1; h < HH; h++)
            for (int c = 0; c < CC; c++)
                if (alpha[h*CC+c] != alpha[c] || lsig[h*CC+c] != lsig[c]) uni = 0;
        g_uniform = uni;
    }
}

__global__ void sq_kernel(const float* __restrict__ x) {
    int t = blockIdx.x * blockDim.x + threadIdx.x;
    if (t >= BB*NN*CC) return;
    int c = t % CC; int bn = t / CC;
    const float* p = x + (size_t)bn * XW + c * DC_;
    float s = 0.f;
#pragma unroll
    for (int d = 0; d < DC_; d++) s += p[d] * p[d];
    g_sq[t] = s;
}

__global__ void convert_kernel(const float* __restrict__ h,
                               const float* __restrict__ wq, const float* __restrict__ wk,
                               const float* __restrict__ wv, const float* __restrict__ wo) {
    int i = blockIdx.x * blockDim.x + threadIdx.x;
    if (i < BB*NN*DM_) g_h16[i] = __float2half_rn(h[i]);
    if (i < DM_*DM_) {
        g_Wq16[i] = __float2half_rn(wq[i]);
        g_Wk16[i] = __float2half_rn(wk[i]);
        g_Wv16[i] = __float2half_rn(wv[i]);
        g_Wo16[i] = __float2half_rn(wo[i]);
    }
}

// ---------------- geodesic bias (fp32) ----------------
__global__ __launch_bounds__(256)
void bias_kernel(const float* __restrict__ x) {
    __shared__ float Xi[64][49];
    __shared__ float Xj[64][49];
    __shared__ float sqi[64][3];
    __shared__ float sqj[64][3];

    const int bh = blockIdx.z;
    const int h2 = bh & (HH-1);
    const int b2 = bh >> 3;
    if (g_uniform && h2 > 0) return;

    const int i0 = blockIdx.y * 64, j0 = blockIdx.x * 64;
    const int tid = threadIdx.x;
    const int tx = tid & 15, ty = tid >> 4;

    const float* xb = x + (size_t)b2 * NN * XW;
#pragma unroll
    for (int t = 0; t < 12; t++) {
        int idx = tid + t * 256;
        int row = idx / XW, col = idx % XW;
        Xi[row][col] = xb[(size_t)(i0 + row) * XW + col];
        Xj[row][col] = xb[(size_t)(j0 + row) * XW + col];
    }
    if (tid < 192) {
        int row = tid / 3, c = tid % 3;
        sqi[row][c] = g_sq[((size_t)b2 * NN + i0 + row) * CC + c];
        sqj[row][c] = g_sq[((size_t)b2 * NN + j0 + row) * CC + c];
    }
    __syncthreads();

    float Acf[CC], Gcf[CC];
#pragma unroll
    for (int c = 0; c < CC; c++) { Acf[c] = g_alpha[h2*CC + c]; Gcf[c] = g_gcoef[h2*CC + c]; }

    float* outp = g_bias + (size_t)(b2*HH + h2) * NN * NN;

#pragma unroll
    for (int r = 0; r < 4; r++) {
        int i = 4*ty + r;
        float4 res;
        float* resp = (float*)&res;
#pragma unroll
        for (int c = 0; c < 4; c++) {
            int j = 4*tx + c;
            float bsum = 0.f;
#pragma unroll
            for (int cm = 0; cm < CC; cm++) {
                float inner = 0.f;
#pragma unroll
                for (int d = 0; d < DC_; d++)
                    inner = fmaf(Xi[i][cm*DC_ + d], Xj[j][cm*DC_ + d], inner);
                float dd = fmaxf(sqi[i][cm] + sqj[j][cm] - 2.f * inner, 0.f);
                bsum = fmaf(Acf[cm], __expf(-dd * Gcf[cm]), bsum);
            }
            resp[c] = bsum;
        }
        *(float4*)(outp + (size_t)(i0 + i) * NN + j0 + 4*tx) = res;
    }
}

// ---------------- HMMA GEMM (128x128 block, K=512, cp.async 3-stage) -------
// stage s: A tile @ s*32768, B tile @ s*32768 + 16384; 3 stages = 96KB
#define GSMEM 98304

__device__ __forceinline__ void gemm_load_stage(const __half* __restrict__ A,
                                                const __half* __restrict__ W,
                                                uint32_t sb, int m0, int o0,
                                                int kt, int stage, int tid) {
    const uint32_t base = sb + (uint32_t)stage * 32768u;
#pragma unroll
    for (int i = 0; i < 4; i++) {
        int idx = tid + i * 256, row = idx >> 3, seg = idx & 7;
        uint32_t sw = swz((uint32_t)(row * 128 + seg * 16));
        cp16(base + sw,          A + (size_t)(m0 + row) * DM_ + kt*64 + seg*8);
        cp16(base + 16384 + sw,  W + (size_t)(o0 + row) * DM_ + kt*64 + seg*8);
    }
}

__device__ __forceinline__ void hmma_mainloop(const __half* __restrict__ A,
                                              const __half* __restrict__ W,
                                              char* smem, int m0, int o0,
                                              float acc[4][4][4]) {
    const int tid = threadIdx.x;
    const int lane = tid & 31, wid = tid >> 5;
    const int wm = wid >> 2, wn = wid & 3;
    const uint32_t sb = smem_u32(smem);

    gemm_load_stage(A, W, sb, m0, o0, 0, 0, tid); CP_COMMIT();
    gemm_load_stage(A, W, sb, m0, o0, 1, 1, tid); CP_COMMIT();

    for (int kt = 0; kt < 8; kt++) {
        CP_WAIT1();
        __syncthreads();
        const uint32_t abase = sb + (uint32_t)(kt % 3) * 32768u;
        const uint32_t bbase = abase + 16384;
#pragma unroll
        for (int ks = 0; ks < 4; ks++) {
            uint32_t af[4][4];
#pragma unroll
            for (int mt = 0; mt < 4; mt++)
                ldm_x4(af[mt], abase + swz((uint32_t)((wm*64 + mt*16 + (lane & 15)) * 128
                                                      + ks*32 + ((lane >> 4) & 1) * 16)));
#pragma unroll
            for (int np = 0; np < 2; np++) {
                uint32_t bf[4];
                ldm_x4(bf, bbase + swz((uint32_t)((wn*32 + np*16 + (lane & 7) + ((lane >> 4) & 1)*8) * 128
                                                  + ks*32 + ((lane >> 3) & 1) * 16)));
#pragma unroll
                for (int mt = 0; mt < 4; mt++) {
                    mma16816(acc[mt][np*2],     af[mt], bf);
                    mma16816(acc[mt][np*2 + 1], af[mt], bf + 2);
                }
            }
        }
        if (kt < 6) gemm_load_stage(A, W, sb, m0, o0, kt + 2, (kt + 2) % 3, tid);
        CP_COMMIT();
    }
}

__global__ __launch_bounds__(256, 2)
void qkv_gemm(const float* __restrict__ bq, const float* __restrict__ bk, const float* __restrict__ bv) {
    extern __shared__ char smem[];
    const int z = blockIdx.z;
    const __half* W = (z == 0) ? g_Wq16 : ((z == 1) ? g_Wk16 : g_Wv16);
    const float* bias = (z == 0) ? bq : ((z == 1) ? bk : bv);
    __half* OUT = (z == 0) ? g_Q16 : ((z == 1) ? g_K16 : g_V16);
    const float scale = (z == 0) ? 0.125f : 1.0f;
    const int m0 = blockIdx.y * 128, o0 = blockIdx.x * 128;

    float acc[4][4][4] = {};
    hmma_mainloop(g_h16, W, smem, m0, o0, acc);

    const int lane = threadIdx.x & 31, wid = threadIdx.x >> 5;
    const int wm = wid >> 2, wn = wid & 3;
    const int g = lane >> 2, t2 = (lane & 3) * 2;
#pragma unroll
    for (int mt = 0; mt < 4; mt++) {
#pragma unroll
        for (int nt = 0; nt < 4; nt++) {
            int o = o0 + wn*32 + nt*8 + t2;
            int hd = o >> 6, dk0 = o & 63;
            float b0 = bias[o], b1 = bias[o + 1];
#pragma unroll
            for (int half = 0; half < 2; half++) {
                int m = m0 + wm*64 + mt*16 + g + half*8;
                int b2 = m >> 10, n2 = m & 1023;
                float v0 = (acc[mt][nt][half*2]     + b0) * scale;
                float v1 = (acc[mt][nt][half*2 + 1] + b1) * scale;
                __half2 hh = __floats2half2_rn(v0, v1);
                *(__half2*)(OUT + (((size_t)(b2*HH + hd)) * NN + n2) * DK_ + dk0) = hh;
            }
        }
    }
}

__global__ __launch_bounds__(256, 2)
void out_gemm(const float* __restrict__ bo, float* __restrict__ out) {
    extern __shared__ char smem[];
    const int m0 = blockIdx.y * 128, o0 = blockIdx.x * 128;

    float acc[4][4][4] = {};
    hmma_mainloop(g_AO16, g_Wo16, smem, m0, o0, acc);

    const int lane = threadIdx.x & 31, wid = threadIdx.x >> 5;
    const int wm = wid >> 2, wn = wid & 3;
    const int g = lane >> 2, t2 = (lane & 3) * 2;
#pragma unroll
    for (int mt = 0; mt < 4; mt++) {
#pragma unroll
        for (int nt = 0; nt < 4; nt++) {
            int o = o0 + wn*32 + nt*8 + t2;
            float b0 = bo[o], b1 = bo[o + 1];
#pragma unroll
            for (int half = 0; half < 2; half++) {
                int m = m0 + wm*64 + mt*16 + g + half*8;
                float* dst = out + (size_t)m * DM_ + o;
                dst[0] = acc[mt][nt][half*2]     + b0;
                dst[1] = acc[mt][nt][half*2 + 1] + b1;
            }
        }
    }
}

// ---------------- HMMA flash attention (cp.async 3-stage K/V) --------------
// smem: Q @0 (16KB); stage s: K @ 16384+s*32768, V @ +16384. Total 112KB.
#define ASMEM 114688

__device__ __forceinline__ void attn_load_kv(const __half* __restrict__ Kb,
                                             const __half* __restrict__ Vb,
                                             uint32_t sb, int j0, int stage, int tid) {
    const uint32_t kbase = sb + 16384u + (uint32_t)stage * 32768u;
#pragma unroll
    for (int i = 0; i < 4; i++) {
        int idx = tid + i * 256, row = idx >> 3, seg = idx & 7;
        uint32_t sw = swz((uint32_t)(row * 128 + seg * 16));
        cp16(kbase + sw,          Kb + (size_t)(j0 + row) * DK_ + seg * 8);
        cp16(kbase + 16384 + sw,  Vb + (size_t)(j0 + row) * DK_ + seg * 8);
    }
}

__global__ __launch_bounds__(256, 1)
void attn_hmma() {
    extern __shared__ char smem[];
    const uint32_t sb = smem_u32(smem);
    const int tid = threadIdx.x;
    const int lane = tid & 31, w = tid >> 5;
    const int g = lane >> 2, t2 = (lane & 3) * 2;

    const int bh = blockIdx.y;
    const int b2 = bh >> 3, h2 = bh & 7;
    const int i0 = blockIdx.x * 128;
    const int heff = g_uniform ? 0 : h2;

    const __half* Kb = g_K16 + (size_t)bh * NN * DK_;
    const __half* Vb = g_V16 + (size_t)bh * NN * DK_;

    // kick off K/V pipeline first (overlap with Q setup)
    attn_load_kv(Kb, Vb, sb, 0,   0, tid); CP_COMMIT();
    attn_load_kv(Kb, Vb, sb, 128, 1, tid); CP_COMMIT();

    // load Q tile [128][64] swizzled — one 16B segment per store
    const __half* Qg = g_Q16 + ((size_t)bh * NN + i0) * DK_;
#pragma unroll
    for (int i = 0; i < 4; i++) {
        int idx = tid + i * 256, row = idx >> 3, seg = idx & 7;
        uint32_t sw = swz((uint32_t)(row * 128 + seg * 16));
        *(uint4*)(smem + sw) = *(const uint4*)(Qg + (size_t)row * DK_ + seg * 8);
    }
    __syncthreads();

    // Q fragments register-resident: 4 k16 steps
    uint32_t qa[4][4];
#pragma unroll
    for (int ks = 0; ks < 4; ks++)
        ldm_x4(qa[ks], sb + swz((uint32_t)((w*16 + (lane & 15)) * 128
                                           + ks*32 + ((lane >> 4) & 1) * 16)));

    float m1 = -1e30f, m2 = -1e30f, l1 = 0.f, l2 = 0.f;
    float o_[8][4] = {};

    const float* Bg = g_bias + ((size_t)(b2*HH + heff) * NN + i0) * NN;

    for (int jt = 0; jt < 8; jt++) {
        const int j0 = jt * 128;
        CP_WAIT1();
        __syncthreads();
        const uint32_t KOFF = 16384u + (uint32_t)(jt % 3) * 32768u;
        const uint32_t VOFF = KOFF + 16384u;

        // S = Q @ K^T : 16 n8 tiles
        float sf[16][4] = {};
#pragma unroll
        for (int np = 0; np < 8; np++) {
#pragma unroll
            for (int ks = 0; ks < 4; ks++) {
                uint32_t bf[4];
                ldm_x4(bf, sb + KOFF + swz((uint32_t)((np*16 + (lane & 7) + ((lane >> 4) & 1)*8) * 128
                                                      + ks*32 + ((lane >> 3) & 1) * 16)));
                mma16816(sf[np*2],     qa[ks], bf);
                mma16816(sf[np*2 + 1], qa[ks], bf + 2);
            }
        }

        // + bias (fp32, direct from L2)
        const float* bp1 = Bg + (size_t)(16*w + g) * NN + j0 + t2;
        const float* bp2 = bp1 + 8 * NN;
#pragma unroll
        for (int nt = 0; nt < 16; nt++) {
            float2 bv1 = *(const float2*)(bp1 + nt*8);
            float2 bv2 = *(const float2*)(bp2 + nt*8);
            sf[nt][0] += bv1.x; sf[nt][1] += bv1.y;
            sf[nt][2] += bv2.x; sf[nt][3] += bv2.y;
        }

        // warp-local online softmax (rows g and g+8 of this warp's slab)
        float mx1 = sf[0][0], mx2 = sf[0][2];
#pragma unroll
        for (int nt = 0; nt < 16; nt++) {
            mx1 = fmaxf(mx1, fmaxf(sf[nt][0], sf[nt][1]));
            mx2 = fmaxf(mx2, fmaxf(sf[nt][2], sf[nt][3]));
        }
        mx1 = fmaxf(mx1, __shfl_xor_sync(0xffffffffu, mx1, 1));
        mx1 = fmaxf(mx1, __shfl_xor_sync(0xffffffffu, mx1, 2));
        mx2 = fmaxf(mx2, __shfl_xor_sync(0xffffffffu, mx2, 1));
        mx2 = fmaxf(mx2, __shfl_xor_sync(0xffffffffu, mx2, 2));

        float n1 = fmaxf(m1, mx1), n2 = fmaxf(m2, mx2);
        float f1 = __expf(m1 - n1), f2 = __expf(m2 - n2);
        float rs1 = 0.f, rs2 = 0.f;
#pragma unroll
        for (int nt = 0; nt < 16; nt++) {
            sf[nt][0] = __expf(sf[nt][0] - n1);
            sf[nt][1] = __expf(sf[nt][1] - n1);
            sf[nt][2] = __expf(sf[nt][2] - n2);
            sf[nt][3] = __expf(sf[nt][3] - n2);
            rs1 += sf[nt][0] + sf[nt][1];
            rs2 += sf[nt][2] + sf[nt][3];
        }
        rs1 += __shfl_xor_sync(0xffffffffu, rs1, 1);
        rs1 += __shfl_xor_sync(0xffffffffu, rs1, 2);
        rs2 += __shfl_xor_sync(0xffffffffu, rs2, 1);
        rs2 += __shfl_xor_sync(0xffffffffu, rs2, 2);
        l1 = l1 * f1 + rs1;  m1 = n1;
        l2 = l2 * f2 + rs2;  m2 = n2;

#pragma unroll
        for (int dt = 0; dt < 8; dt++) {
            o_[dt][0] *= f1; o_[dt][1] *= f1;
            o_[dt][2] *= f2; o_[dt][3] *= f2;
        }

        // O += P @ V : k over j (8 k16 chunks), n over d (8 n8 tiles)
#pragma unroll
        for (int kk = 0; kk < 8; kk++) {
            uint32_t pa[4];
            {
                __half2 h0 = __floats2half2_rn(sf[2*kk][0],   sf[2*kk][1]);
                __half2 h1 = __floats2half2_rn(sf[2*kk][2],   sf[2*kk][3]);
                __half2 h2_ = __floats2half2_rn(sf[2*kk+1][0], sf[2*kk+1][1]);
                __half2 h3 = __floats2half2_rn(sf[2*kk+1][2], sf[2*kk+1][3]);
                pa[0] = *(uint32_t*)&h0; pa[1] = *(uint32_t*)&h1;
                pa[2] = *(uint32_t*)&h2_; pa[3] = *(uint32_t*)&h3;
            }
#pragma unroll
            for (int dp = 0; dp < 4; dp++) {
                uint32_t bf[4];
                ldm_x4_t(bf, sb + VOFF + swz((uint32_t)((kk*16 + (lane & 7) + ((lane >> 3) & 1)*8) * 128
                                                        + dp*32 + ((lane >> 4) & 1) * 16)));
                mma16816(o_[dp*2],     pa, bf);
                mma16816(o_[dp*2 + 1], pa, bf + 2);
            }
        }

        if (jt < 6) attn_load_kv(Kb, Vb, sb, (jt + 2) * 128, (jt + 2) % 3, tid);
        CP_COMMIT();
    }

    // epilogue
    float i1 = 1.0f / l1, i2 = 1.0f / l2;
    __half* dst1 = g_AO16 + ((size_t)b2 * NN + i0 + 16*w + g)     * DM_ + h2*DK_ + t2;
    __half* dst2 = g_AO16 + ((size_t)b2 * NN + i0 + 16*w + g + 8) * DM_ + h2*DK_ + t2;
#pragma unroll
    for (int dt = 0; dt < 8; dt++) {
        *(__half2*)(dst1 + dt*8) = __floats2half2_rn(o_[dt][0] * i1, o_[dt][1] * i1);
        *(__half2*)(dst2 + dt*8) = __floats2half2_rn(o_[dt][2] * i2, o_[dt][3] * i2);
    }
}

// ---------------- launcher ----------------
extern "C" void kernel_launch(void* const* d_in, const int* in_sizes, int n_in,
                              void* d_out, int out_size) {
    const float* h    = (const float*)d_in[0];
    const float* x    = (const float*)d_in[1];
    const float* Wq   = (const float*)d_in[2];
    const float* bq   = (const float*)d_in[3];
    const float* Wk   = (const float*)d_in[4];
    const float* bk   = (const float*)d_in[5];
    const float* Wv   = (const float*)d_in[6];
    const float* bv   = (const float*)d_in[7];
    const float* Wo   = (const float*)d_in[8];
    const float* bo   = (const float*)d_in[9];
    const float* alpha= (const float*)d_in[10];
    const float* lsig = (const float*)d_in[11];
    float* out = (float*)d_out;

    cudaFuncSetAttribute(qkv_gemm, cudaFuncAttributeMaxDynamicSharedMemorySize, GSMEM);
    cudaFuncSetAttribute(out_gemm, cudaFuncAttributeMaxDynamicSharedMemorySize, GSMEM);
    cudaFuncSetAttribute(attn_hmma, cudaFuncAttributeMaxDynamicSharedMemorySize, ASMEM);

    prep_coef_kernel<<<1, 32>>>(alpha, lsig);
    sq_kernel<<<(BB*NN*CC + 127)/128, 128>>>(x);
    convert_kernel<<<(BB*NN*DM_ + 255)/256, 256>>>(h, Wq, Wk, Wv, Wo);

    qkv_gemm<<<dim3(DM_/128, (BB*NN)/128, 3), 256, GSMEM>>>(bq, bk, bv);

    bias_kernel<<<dim3(NN/64, NN/64, BB*HH), 256>>>(x);

    attn_hmma<<<dim3(NN/128, BB*HH), 256, ASMEM>>>();

    out_gemm<<<dim3(DM_/128, (BB*NN)/128), 256, GSMEM>>>(bo, out);
}

// round 10
// speedup vs baseline: 5.1705x; 1.0362x over previous
#include <cuda_runtime.h>
#include <cuda_fp16.h>
#include <math.h>
#include <stdint.h>

#define BB  4
#define NN  1024
#define DM_ 512
#define HH  8
#define CC  3
#define DC_ 16
#define DK_ 64
#define XW  (CC*DC_)

// ---------------- device scratch (16B-aligned for vector ld/st) ------------
__device__ __align__(16) __half g_h16[(size_t)BB*NN*DM_];
__device__ __align__(16) __half g_Wq16[DM_*DM_];
__device__ __align__(16) __half g_Wk16[DM_*DM_];
__device__ __align__(16) __half g_Wv16[DM_*DM_];
__device__ __align__(16) __half g_Wo16[DM_*DM_];
__device__ __align__(16) __half g_Q16[(size_t)BB*HH*NN*DK_];
__device__ __align__(16) __half g_K16[(size_t)BB*HH*NN*DK_];
__device__ __align__(16) __half g_V16[(size_t)BB*HH*NN*DK_];
__device__ __align__(16) __half g_AO16[(size_t)BB*NN*DM_];
__device__ __align__(16) float  g_bias[(size_t)BB*HH*NN*NN];
__device__ __align__(16) float  g_sq[BB*NN*CC];
__device__ __align__(16) float  g_alpha[HH*CC];
__device__ __align__(16) float  g_gcoef[HH*CC];
__device__ int    g_uniform;

// ---------------- helpers ----------------
__device__ __forceinline__ uint32_t smem_u32(const void* p) {
    uint32_t a;
    asm("{ .reg .u64 t; cvta.to.shared.u64 t, %1; cvt.u32.u64 %0, t; }" : "=r"(a) : "l"(p));
    return a;
}
__device__ __forceinline__ uint32_t swz(uint32_t o) { return o ^ ((o >> 3) & 0x70); }

__device__ __forceinline__ void mma16816(float* d, const uint32_t* a, const uint32_t* b) {
    asm volatile("mma.sync.aligned.m16n8k16.row.col.f32.f16.f16.f32 "
        "{%0,%1,%2,%3}, {%4,%5,%6,%7}, {%8,%9}, {%0,%1,%2,%3};"
        : "+f"(d[0]), "+f"(d[1]), "+f"(d[2]), "+f"(d[3])
        : "r"(a[0]), "r"(a[1]), "r"(a[2]), "r"(a[3]), "r"(b[0]), "r"(b[1]));
}
__device__ __forceinline__ void ldm_x4(uint32_t* r, uint32_t addr) {
    asm volatile("ldmatrix.sync.aligned.m8n8.x4.shared.b16 {%0,%1,%2,%3}, [%4];"
        : "=r"(r[0]), "=r"(r[1]), "=r"(r[2]), "=r"(r[3]) : "r"(addr));
}
__device__ __forceinline__ void ldm_x4_t(uint32_t* r, uint32_t addr) {
    asm volatile("ldmatrix.sync.aligned.m8n8.x4.trans.shared.b16 {%0,%1,%2,%3}, [%4];"
        : "=r"(r[0]), "=r"(r[1]), "=r"(r[2]), "=r"(r[3]) : "r"(addr));
}
__device__ __forceinline__ void cp16(uint32_t saddr, const void* gptr) {
    asm volatile("cp.async.cg.shared.global [%0], [%1], 16;" :: "r"(saddr), "l"(gptr));
}
#define CP_COMMIT() asm volatile("cp.async.commit_group;" ::: "memory")
#define CP_WAIT1()  asm volatile("cp.async.wait_group 1;" ::: "memory")
#define CP_WAIT0()  asm volatile("cp.async.wait_group 0;" ::: "memory")

// ---------------- small prep kernels ----------------
__global__ void prep_coef_kernel(const float* __restrict__ alpha, const float* __restrict__ lsig) {
    int i = threadIdx.x;   // 32 threads, HH*CC = 24 live
    int ok = 1;
    if (i < HH*CC) {
        float a = alpha[i], l = lsig[i];
        float s = expf(l);
        if (s < 1e-4f) s = 1e-4f;
        g_gcoef[i] = 1.0f / (2.0f * s * s);
        g_alpha[i] = a;
        ok = (a == alpha[i % CC]) && (l == lsig[i % CC]);
    }
    int uni = __all_sync(0xffffffffu, ok);
    if (i == 0) g_uniform = uni;
}

__global__ void sq_kernel(const float* __restrict__ x) {
    int t = blockIdx.x * blockDim.x + threadIdx.x;
    if (t >= BB*NN*CC) return;
    int c = t % CC; int bn = t / CC;
    const float* p = x + (size_t)bn * XW + c * DC_;
    float s = 0.f;
#pragma unroll
    for (int d = 0; d < DC_; d++) s += p[d] * p[d];
    g_sq[t] = s;
}

__global__ void convert_kernel(const float* __restrict__ h,
                               const float* __restrict__ wq, const float* __restrict__ wk,
                               const float* __restrict__ wv, const float* __restrict__ wo) {
    int i = blockIdx.x * blockDim.x + threadIdx.x;
    if (i < BB*NN*DM_) g_h16[i] = __float2half_rn(h[i]);
    if (i < DM_*DM_) {
        g_Wq16[i] = __float2half_rn(wq[i]);
        g_Wk16[i] = __float2half_rn(wk[i]);
        g_Wv16[i] = __float2half_rn(wv[i]);
        g_Wo16[i] = __float2half_rn(wo[i]);
    }
}

// ---------------- geodesic bias (fp32) ----------------
__global__ __launch_bounds__(256)
void bias_kernel(const float* __restrict__ x) {
    __shared__ float Xi[64][49];
    __shared__ float Xj[64][49];
    __shared__ float sqi[64][3];
    __shared__ float sqj[64][3];

    const int bh = blockIdx.z;
    const int h2 = bh & (HH-1);
    const int b2 = bh >> 3;
    if (g_uniform && h2 > 0) return;

    const int i0 = blockIdx.y * 64, j0 = blockIdx.x * 64;
    const int tid = threadIdx.x;
    const int tx = tid & 15, ty = tid >> 4;

    const float* xb = x + (size_t)b2 * NN * XW;
#pragma unroll
    for (int t = 0; t < 12; t++) {
        int idx = tid + t * 256;
        int row = idx / XW, col = idx % XW;
        Xi[row][col] = xb[(size_t)(i0 + row) * XW + col];
        Xj[row][col] = xb[(size_t)(j0 + row) * XW + col];
    }
    if (tid < 192) {
        int row = tid / 3, c = tid % 3;
        sqi[row][c] = g_sq[((size_t)b2 * NN + i0 + row) * CC + c];
        sqj[row][c] = g_sq[((size_t)b2 * NN + j0 + row) * CC + c];
    }
    __syncthreads();

    float Acf[CC], Gcf[CC];
#pragma unroll
    for (int c = 0; c < CC; c++) { Acf[c] = g_alpha[h2*CC + c]; Gcf[c] = g_gcoef[h2*CC + c]; }

    float* outp = g_bias + (size_t)(b2*HH + h2) * NN * NN;

#pragma unroll
    for (int r = 0; r < 4; r++) {
        int i = 4*ty + r;
        float4 res;
        float* resp = (float*)&res;
#pragma unroll
        for (int c = 0; c < 4; c++) {
            int j = 4*tx + c;
            float bsum = 0.f;
#pragma unroll
            for (int cm = 0; cm < CC; cm++) {
                float inner = 0.f;
#pragma unroll
                for (int d = 0; d < DC_; d++)
                    inner = fmaf(Xi[i][cm*DC_ + d], Xj[j][cm*DC_ + d], inner);
                float dd = fmaxf(sqi[i][cm] + sqj[j][cm] - 2.f * inner, 0.f);
                bsum = fmaf(Acf[cm], __expf(-dd * Gcf[cm]), bsum);
            }
            resp[c] = bsum;
        }
        *(float4*)(outp + (size_t)(i0 + i) * NN + j0 + 4*tx) = res;
    }
}

// ---------------- HMMA GEMM (128x128 block, K=512, cp.async 3-stage) -------
// stage s: A tile @ s*32768, B tile @ s*32768 + 16384; 3 stages = 96KB
#define GSMEM 98304

__device__ __forceinline__ void gemm_load_stage(const __half* __restrict__ A,
                                                const __half* __restrict__ W,
                                                uint32_t sb, int m0, int o0,
                                                int kt, int stage, int tid) {
    const uint32_t base = sb + (uint32_t)stage * 32768u;
#pragma unroll
    for (int i = 0; i < 4; i++) {
        int idx = tid + i * 256, row = idx >> 3, seg = idx & 7;
        uint32_t sw = swz((uint32_t)(row * 128 + seg * 16));
        cp16(base + sw,          A + (size_t)(m0 + row) * DM_ + kt*64 + seg*8);
        cp16(base + 16384 + sw,  W + (size_t)(o0 + row) * DM_ + kt*64 + seg*8);
    }
}

__device__ __forceinline__ void hmma_mainloop(const __half* __restrict__ A,
                                              const __half* __restrict__ W,
                                              char* smem, int m0, int o0,
                                              float acc[4][4][4]) {
    const int tid = threadIdx.x;
    const int lane = tid & 31, wid = tid >> 5;
    const int wm = wid >> 2, wn = wid & 3;
    const uint32_t sb = smem_u32(smem);

    gemm_load_stage(A, W, sb, m0, o0, 0, 0, tid); CP_COMMIT();
    gemm_load_stage(A, W, sb, m0, o0, 1, 1, tid); CP_COMMIT();

    for (int kt = 0; kt < 8; kt++) {
        CP_WAIT1();
        __syncthreads();
        const uint32_t abase = sb + (uint32_t)(kt % 3) * 32768u;
        const uint32_t bbase = abase + 16384;
#pragma unroll
        for (int ks = 0; ks < 4; ks++) {
            uint32_t af[4][4];
#pragma unroll
            for (int mt = 0; mt < 4; mt++)
                ldm_x4(af[mt], abase + swz((uint32_t)((wm*64 + mt*16 + (lane & 15)) * 128
                                                      + ks*32 + ((lane >> 4) & 1) * 16)));
#pragma unroll
            for (int np = 0; np < 2; np++) {
                uint32_t bf[4];
                ldm_x4(bf, bbase + swz((uint32_t)((wn*32 + np*16 + (lane & 7) + ((lane >> 4) & 1)*8) * 128
                                                  + ks*32 + ((lane >> 3) & 1) * 16)));
#pragma unroll
                for (int mt = 0; mt < 4; mt++) {
                    mma16816(acc[mt][np*2],     af[mt], bf);
                    mma16816(acc[mt][np*2 + 1], af[mt], bf + 2);
                }
            }
        }
        if (kt < 6) gemm_load_stage(A, W, sb, m0, o0, kt + 2, (kt + 2) % 3, tid);
        CP_COMMIT();
    }
}

__global__ __launch_bounds__(256, 2)
void qkv_gemm(const float* __restrict__ bq, const float* __restrict__ bk, const float* __restrict__ bv) {
    extern __shared__ char smem[];
    const int z = blockIdx.z;
    const __half* W = (z == 0) ? g_Wq16 : ((z == 1) ? g_Wk16 : g_Wv16);
    const float* bias = (z == 0) ? bq : ((z == 1) ? bk : bv);
    __half* OUT = (z == 0) ? g_Q16 : ((z == 1) ? g_K16 : g_V16);
    const float scale = (z == 0) ? 0.125f : 1.0f;
    const int m0 = blockIdx.y * 128, o0 = blockIdx.x * 128;

    float acc[4][4][4] = {};
    hmma_mainloop(g_h16, W, smem, m0, o0, acc);

    const int lane = threadIdx.x & 31, wid = threadIdx.x >> 5;
    const int wm = wid >> 2, wn = wid & 3;
    const int g = lane >> 2, t2 = (lane & 3) * 2;
#pragma unroll
    for (int mt = 0; mt < 4; mt++) {
#pragma unroll
        for (int nt = 0; nt < 4; nt++) {
            int o = o0 + wn*32 + nt*8 + t2;
            int hd = o >> 6, dk0 = o & 63;
            float b0 = bias[o], b1 = bias[o + 1];
#pragma unroll
            for (int half = 0; half < 2; half++) {
                int m = m0 + wm*64 + mt*16 + g + half*8;
                int b2 = m >> 10, n2 = m & 1023;
                float v0 = (acc[mt][nt][half*2]     + b0) * scale;
                float v1 = (acc[mt][nt][half*2 + 1] + b1) * scale;
                __half2 hh = __floats2half2_rn(v0, v1);
                *(__half2*)(OUT + (((size_t)(b2*HH + hd)) * NN + n2) * DK_ + dk0) = hh;
            }
        }
    }
}

__global__ __launch_bounds__(256, 2)
void out_gemm(const float* __restrict__ bo, float* __restrict__ out) {
    extern __shared__ char smem[];
    const int m0 = blockIdx.y * 128, o0 = blockIdx.x * 128;

    float acc[4][4][4] = {};
    hmma_mainloop(g_AO16, g_Wo16, smem, m0, o0, acc);

    const int lane = threadIdx.x & 31, wid = threadIdx.x >> 5;
    const int wm = wid >> 2, wn = wid & 3;
    const int g = lane >> 2, t2 = (lane & 3) * 2;
#pragma unroll
    for (int mt = 0; mt < 4; mt++) {
#pragma unroll
        for (int nt = 0; nt < 4; nt++) {
            int o = o0 + wn*32 + nt*8 + t2;
            float b0 = bo[o], b1 = bo[o + 1];
#pragma unroll
            for (int half = 0; half < 2; half++) {
                int m = m0 + wm*64 + mt*16 + g + half*8;
                float* dst = out + (size_t)m * DM_ + o;
                dst[0] = acc[mt][nt][half*2]     + b0;
                dst[1] = acc[mt][nt][half*2 + 1] + b1;
            }
        }
    }
}

// ---------------- HMMA flash attention (cp.async 2-stage K/V, 2 blk/SM) ----
// smem: Q @0 (16KB); stage s (0/1): K @ 16384+s*32768, V @ +16384. Total 80KB.
#define ASMEM 81920

__device__ __forceinline__ void attn_load_kv(const __half* __restrict__ Kb,
                                             const __half* __restrict__ Vb,
                                             uint32_t sb, int j0, int stage, int tid) {
    const uint32_t kbase = sb + 16384u + (uint32_t)stage * 32768u;
#pragma unroll
    for (int i = 0; i < 4; i++) {
        int idx = tid + i * 256, row = idx >> 3, seg = idx & 7;
        uint32_t sw = swz((uint32_t)(row * 128 + seg * 16));
        cp16(kbase + sw,          Kb + (size_t)(j0 + row) * DK_ + seg * 8);
        cp16(kbase + 16384 + sw,  Vb + (size_t)(j0 + row) * DK_ + seg * 8);
    }
}

__global__ __launch_bounds__(256, 2)
void attn_hmma() {
    extern __shared__ char smem[];
    const uint32_t sb = smem_u32(smem);
    const int tid = threadIdx.x;
    const int lane = tid & 31, w = tid >> 5;
    const int g = lane >> 2, t2 = (lane & 3) * 2;

    const int bh = blockIdx.y;
    const int b2 = bh >> 3, h2 = bh & 7;
    const int i0 = blockIdx.x * 128;
    const int heff = g_uniform ? 0 : h2;

    const __half* Kb = g_K16 + (size_t)bh * NN * DK_;
    const __half* Vb = g_V16 + (size_t)bh * NN * DK_;

    // kick off stage 0 (overlap with Q setup)
    attn_load_kv(Kb, Vb, sb, 0, 0, tid); CP_COMMIT();

    // load Q tile [128][64] swizzled — one 16B segment per store
    const __half* Qg = g_Q16 + ((size_t)bh * NN + i0) * DK_;
#pragma unroll
    for (int i = 0; i < 4; i++) {
        int idx = tid + i * 256, row = idx >> 3, seg = idx & 7;
        uint32_t sw = swz((uint32_t)(row * 128 + seg * 16));
        *(uint4*)(smem + sw) = *(const uint4*)(Qg + (size_t)row * DK_ + seg * 8);
    }
    __syncthreads();

    // Q fragments register-resident: 4 k16 steps
    uint32_t qa[4][4];
#pragma unroll
    for (int ks = 0; ks < 4; ks++)
        ldm_x4(qa[ks], sb + swz((uint32_t)((w*16 + (lane & 15)) * 128
                                           + ks*32 + ((lane >> 4) & 1) * 16)));

    float m1 = -1e30f, m2 = -1e30f, l1 = 0.f, l2 = 0.f;
    float o_[8][4] = {};

    const float* Bg = g_bias + ((size_t)(b2*HH + heff) * NN + i0) * NN;

    for (int jt = 0; jt < 8; jt++) {
        const int j0 = jt * 128;
        CP_WAIT0();
        __syncthreads();
        // issue next stage now — overlaps with this tile's compute
        if (jt < 7) { attn_load_kv(Kb, Vb, sb, (jt + 1) * 128, (jt + 1) & 1, tid); CP_COMMIT(); }

        const uint32_t KOFF = 16384u + (uint32_t)(jt & 1) * 32768u;
        const uint32_t VOFF = KOFF + 16384u;

        // S = Q @ K^T : 16 n8 tiles
        float sf[16][4] = {};
#pragma unroll
        for (int np = 0; np < 8; np++) {
#pragma unroll
            for (int ks = 0; ks < 4; ks++) {
                uint32_t bf[4];
                ldm_x4(bf, sb + KOFF + swz((uint32_t)((np*16 + (lane & 7) + ((lane >> 4) & 1)*8) * 128
                                                      + ks*32 + ((lane >> 3) & 1) * 16)));
                mma16816(sf[np*2],     qa[ks], bf);
                mma16816(sf[np*2 + 1], qa[ks], bf + 2);
            }
        }

        // + bias (fp32, direct from L2)
        const float* bp1 = Bg + (size_t)(16*w + g) * NN + j0 + t2;
        const float* bp2 = bp1 + 8 * NN;
#pragma unroll
        for (int nt = 0; nt < 16; nt++) {
            float2 bv1 = *(const float2*)(bp1 + nt*8);
            float2 bv2 = *(const float2*)(bp2 + nt*8);
            sf[nt][0] += bv1.x; sf[nt][1] += bv1.y;
            sf[nt][2] += bv2.x; sf[nt][3] += bv2.y;
        }

        // warp-local online softmax (rows g and g+8 of this warp's slab)
        float mx1 = sf[0][0], mx2 = sf[0][2];
#pragma unroll
        for (int nt = 0; nt < 16; nt++) {
            mx1 = fmaxf(mx1, fmaxf(sf[nt][0], sf[nt][1]));
            mx2 = fmaxf(mx2, fmaxf(sf[nt][2], sf[nt][3]));
        }
        mx1 = fmaxf(mx1, __shfl_xor_sync(0xffffffffu, mx1, 1));
        mx1 = fmaxf(mx1, __shfl_xor_sync(0xffffffffu, mx1, 2));
        mx2 = fmaxf(mx2, __shfl_xor_sync(0xffffffffu, mx2, 1));
        mx2 = fmaxf(mx2, __shfl_xor_sync(0xffffffffu, mx2, 2));

        float n1 = fmaxf(m1, mx1), n2 = fmaxf(m2, mx2);
        float f1 = __expf(m1 - n1), f2 = __expf(m2 - n2);
        float rs1 = 0.f, rs2 = 0.f;
#pragma unroll
        for (int nt = 0; nt < 16; nt++) {
            sf[nt][0] = __expf(sf[nt][0] - n1);
            sf[nt][1] = __expf(sf[nt][1] - n1);
            sf[nt][2] = __expf(sf[nt][2] - n2);
            sf[nt][3] = __expf(sf[nt][3] - n2);
            rs1 += sf[nt][0] + sf[nt][1];
            rs2 += sf[nt][2] + sf[nt][3];
        }
        rs1 += __shfl_xor_sync(0xffffffffu, rs1, 1);
        rs1 += __shfl_xor_sync(0xffffffffu, rs1, 2);
        rs2 += __shfl_xor_sync(0xffffffffu, rs2, 1);
        rs2 += __shfl_xor_sync(0xffffffffu, rs2, 2);
        l1 = l1 * f1 + rs1;  m1 = n1;
        l2 = l2 * f2 + rs2;  m2 = n2;

#pragma unroll
        for (int dt = 0; dt < 8; dt++) {
            o_[dt][0] *= f1; o_[dt][1] *= f1;
            o_[dt][2] *= f2; o_[dt][3] *= f2;
        }

        // O += P @ V : k over j (8 k16 chunks), n over d (8 n8 tiles)
#pragma unroll
        for (int kk = 0; kk < 8; kk++) {
            uint32_t pa[4];
            {
                __half2 h0 = __floats2half2_rn(sf[2*kk][0],   sf[2*kk][1]);
                __half2 h1 = __floats2half2_rn(sf[2*kk][2],   sf[2*kk][3]);
                __half2 h2_ = __floats2half2_rn(sf[2*kk+1][0], sf[2*kk+1][1]);
                __half2 h3 = __floats2half2_rn(sf[2*kk+1][2], sf[2*kk+1][3]);
                pa[0] = *(uint32_t*)&h0; pa[1] = *(uint32_t*)&h1;
                pa[2] = *(uint32_t*)&h2_; pa[3] = *(uint32_t*)&h3;
            }
#pragma unroll
            for (int dp = 0; dp < 4; dp++) {
                uint32_t bf[4];
                ldm_x4_t(bf, sb + VOFF + swz((uint32_t)((kk*16 + (lane & 7) + ((lane >> 3) & 1)*8) * 128
                                                        + dp*32 + ((lane >> 4) & 1) * 16)));
                mma16816(o_[dp*2],     pa, bf);
                mma16816(o_[dp*2 + 1], pa, bf + 2);
            }
        }
    }

    // epilogue
    float i1 = 1.0f / l1, i2 = 1.0f / l2;
    __half* dst1 = g_AO16 + ((size_t)b2 * NN + i0 + 16*w + g)     * DM_ + h2*DK_ + t2;
    __half* dst2 = g_AO16 + ((size_t)b2 * NN + i0 + 16*w + g + 8) * DM_ + h2*DK_ + t2;
#pragma unroll
    for (int dt = 0; dt < 8; dt++) {
        *(__half2*)(dst1 + dt*8) = __floats2half2_rn(o_[dt][0] * i1, o_[dt][1] * i1);
        *(__half2*)(dst2 + dt*8) = __floats2half2_rn(o_[dt][2] * i2, o_[dt][3] * i2);
    }
}

// ---------------- launcher ----------------
extern "C" void kernel_launch(void* const* d_in, const int* in_sizes, int n_in,
                              void* d_out, int out_size) {
    const float* h    = (const float*)d_in[0];
    const float* x    = (const float*)d_in[1];
    const float* Wq   = (const float*)d_in[2];
    const float* bq   = (const float*)d_in[3];
    const float* Wk   = (const float*)d_in[4];
    const float* bk   = (const float*)d_in[5];
    const float* Wv   = (const float*)d_in[6];
    const float* bv   = (const float*)d_in[7];
    const float* Wo   = (const float*)d_in[8];
    const float* bo   = (const float*)d_in[9];
    const float* alpha= (const float*)d_in[10];
    const float* lsig = (const float*)d_in[11];
    float* out = (float*)d_out;

    cudaFuncSetAttribute(qkv_gemm, cudaFuncAttributeMaxDynamicSharedMemorySize, GSMEM);
    cudaFuncSetAttribute(out_gemm, cudaFuncAttributeMaxDynamicSharedMemorySize, GSMEM);
    cudaFuncSetAttribute(attn_hmma, cudaFuncAttributeMaxDynamicSharedMemorySize, ASMEM);

    prep_coef_kernel<<<1, 32>>>(alpha, lsig);
    sq_kernel<<<(BB*NN*CC + 127)/128, 128>>>(x);
    convert_kernel<<<(BB*NN*DM_ + 255)/256, 256>>>(h, Wq, Wk, Wv, Wo);

    qkv_gemm<<<dim3(DM_/128, (BB*NN)/128, 3), 256, GSMEM>>>(bq, bk, bv);

    bias_kernel<<<dim3(NN/64, NN/64, BB*HH), 256>>>(x);

    attn_hmma<<<dim3(NN/128, BB*HH), 256, ASMEM>>>();

    out_gemm<<<dim3(DM_/128, (BB*NN)/128), 256, GSMEM>>>(bo, out);
}

// round 11
// speedup vs baseline: 5.2287x; 1.0113x over previous
#include <cuda_runtime.h>
#include <cuda_fp16.h>
#include <math.h>
#include <stdint.h>

#define BB  4
#define NN  1024
#define DM_ 512
#define HH  8
#define CC  3
#define DC_ 16
#define DK_ 64
#define XW  (CC*DC_)

// ---------------- device scratch (16B-aligned for vector ld/st) ------------
__device__ __align__(16) __half g_h16[(size_t)BB*NN*DM_];
__device__ __align__(16) __half g_Wq16[DM_*DM_];
__device__ __align__(16) __half g_Wk16[DM_*DM_];
__device__ __align__(16) __half g_Wv16[DM_*DM_];
__device__ __align__(16) __half g_Wo16[DM_*DM_];
__device__ __align__(16) __half g_Q16[(size_t)BB*HH*NN*DK_];
__device__ __align__(16) __half g_K16[(size_t)BB*HH*NN*DK_];
__device__ __align__(16) __half g_V16[(size_t)BB*HH*NN*DK_];
__device__ __align__(16) __half g_AO16[(size_t)BB*NN*DM_];
__device__ __align__(16) float  g_bias[(size_t)BB*HH*NN*NN];
__device__ __align__(16) float  g_sq[BB*NN*CC];
__device__ __align__(16) float  g_alpha[HH*CC];
__device__ __align__(16) float  g_gcoef[HH*CC];
__device__ int    g_uniform;

// ---------------- helpers ----------------
__device__ __forceinline__ uint32_t smem_u32(const void* p) {
    uint32_t a;
    asm("{ .reg .u64 t; cvta.to.shared.u64 t, %1; cvt.u32.u64 %0, t; }" : "=r"(a) : "l"(p));
    return a;
}
__device__ __forceinline__ uint32_t swz(uint32_t o) { return o ^ ((o >> 3) & 0x70); }

__device__ __forceinline__ void mma16816(float* d, const uint32_t* a, const uint32_t* b) {
    asm volatile("mma.sync.aligned.m16n8k16.row.col.f32.f16.f16.f32 "
        "{%0,%1,%2,%3}, {%4,%5,%6,%7}, {%8,%9}, {%0,%1,%2,%3};"
        : "+f"(d[0]), "+f"(d[1]), "+f"(d[2]), "+f"(d[3])
        : "r"(a[0]), "r"(a[1]), "r"(a[2]), "r"(a[3]), "r"(b[0]), "r"(b[1]));
}
__device__ __forceinline__ void ldm_x4(uint32_t* r, uint32_t addr) {
    asm volatile("ldmatrix.sync.aligned.m8n8.x4.shared.b16 {%0,%1,%2,%3}, [%4];"
        : "=r"(r[0]), "=r"(r[1]), "=r"(r[2]), "=r"(r[3]) : "r"(addr));
}
__device__ __forceinline__ void ldm_x4_t(uint32_t* r, uint32_t addr) {
    asm volatile("ldmatrix.sync.aligned.m8n8.x4.trans.shared.b16 {%0,%1,%2,%3}, [%4];"
        : "=r"(r[0]), "=r"(r[1]), "=r"(r[2]), "=r"(r[3]) : "r"(addr));
}
__device__ __forceinline__ void cp16(uint32_t saddr, const void* gptr) {
    asm volatile("cp.async.cg.shared.global [%0], [%1], 16;" :: "r"(saddr), "l"(gptr));
}
#define CP_COMMIT() asm volatile("cp.async.commit_group;" ::: "memory")
#define CP_WAIT1()  asm volatile("cp.async.wait_group 1;" ::: "memory")
#define CP_WAIT0()  asm volatile("cp.async.wait_group 0;" ::: "memory")

// ---------------- small prep kernels ----------------
__global__ void prep_coef_kernel(const float* __restrict__ alpha, const float* __restrict__ lsig) {
    int i = threadIdx.x;   // 32 threads, HH*CC = 24 live
    int ok = 1;
    if (i < HH*CC) {
        float a = alpha[i], l = lsig[i];
        float s = expf(l);
        if (s < 1e-4f) s = 1e-4f;
        g_gcoef[i] = 1.0f / (2.0f * s * s);
        g_alpha[i] = a;
        ok = (a == alpha[i % CC]) && (l == lsig[i % CC]);
    }
    int uni = __all_sync(0xffffffffu, ok);
    if (i == 0) g_uniform = uni;
}

__global__ void sq_kernel(const float* __restrict__ x) {
    int t = blockIdx.x * blockDim.x + threadIdx.x;
    if (t >= BB*NN*CC) return;
    int c = t % CC; int bn = t / CC;
    const float* p = x + (size_t)bn * XW + c * DC_;
    float s = 0.f;
#pragma unroll
    for (int d = 0; d < DC_; d++) s += p[d] * p[d];
    g_sq[t] = s;
}

__global__ void convert_kernel(const float* __restrict__ h,
                               const float* __restrict__ wq, const float* __restrict__ wk,
                               const float* __restrict__ wv, const float* __restrict__ wo) {
    int i = blockIdx.x * blockDim.x + threadIdx.x;
    if (i < BB*NN*DM_) g_h16[i] = __float2half_rn(h[i]);
    if (i < DM_*DM_) {
        g_Wq16[i] = __float2half_rn(wq[i]);
        g_Wk16[i] = __float2half_rn(wk[i]);
        g_Wv16[i] = __float2half_rn(wv[i]);
        g_Wo16[i] = __float2half_rn(wo[i]);
    }
}

// ---------------- geodesic bias (fp32) ----------------
__global__ __launch_bounds__(256)
void bias_kernel(const float* __restrict__ x) {
    __shared__ float Xi[64][49];
    __shared__ float Xj[64][49];
    __shared__ float sqi[64][3];
    __shared__ float sqj[64][3];

    const int bh = blockIdx.z;
    const int h2 = bh & (HH-1);
    const int b2 = bh >> 3;
    if (g_uniform && h2 > 0) return;

    const int i0 = blockIdx.y * 64, j0 = blockIdx.x * 64;
    const int tid = threadIdx.x;
    const int tx = tid & 15, ty = tid >> 4;

    const float* xb = x + (size_t)b2 * NN * XW;
#pragma unroll
    for (int t = 0; t < 12; t++) {
        int idx = tid + t * 256;
        int row = idx / XW, col = idx % XW;
        Xi[row][col] = xb[(size_t)(i0 + row) * XW + col];
        Xj[row][col] = xb[(size_t)(j0 + row) * XW + col];
    }
    if (tid < 192) {
        int row = tid / 3, c = tid % 3;
        sqi[row][c] = g_sq[((size_t)b2 * NN + i0 + row) * CC + c];
        sqj[row][c] = g_sq[((size_t)b2 * NN + j0 + row) * CC + c];
    }
    __syncthreads();

    float Acf[CC], Gcf[CC];
#pragma unroll
    for (int c = 0; c < CC; c++) { Acf[c] = g_alpha[h2*CC + c]; Gcf[c] = g_gcoef[h2*CC + c]; }

    float* outp = g_bias + (size_t)(b2*HH + h2) * NN * NN;

#pragma unroll
    for (int r = 0; r < 4; r++) {
        int i = 4*ty + r;
        float4 res;
        float* resp = (float*)&res;
#pragma unroll
        for (int c = 0; c < 4; c++) {
            int j = 4*tx + c;
            float bsum = 0.f;
#pragma unroll
            for (int cm = 0; cm < CC; cm++) {
                float inner = 0.f;
#pragma unroll
                for (int d = 0; d < DC_; d++)
                    inner = fmaf(Xi[i][cm*DC_ + d], Xj[j][cm*DC_ + d], inner);
                float dd = fmaxf(sqi[i][cm] + sqj[j][cm] - 2.f * inner, 0.f);
                bsum = fmaf(Acf[cm], __expf(-dd * Gcf[cm]), bsum);
            }
            resp[c] = bsum;
        }
        *(float4*)(outp + (size_t)(i0 + i) * NN + j0 + 4*tx) = res;
    }
}

// ---------------- HMMA GEMM (128x128 block, K=512, cp.async 3-stage) -------
// stage s: A tile @ s*32768, B tile @ s*32768 + 16384; 3 stages = 96KB
#define GSMEM 98304

__device__ __forceinline__ void gemm_load_stage(const __half* __restrict__ A,
                                                const __half* __restrict__ W,
                                                uint32_t sb, int m0, int o0,
                                                int kt, int stage, int tid) {
    const uint32_t base = sb + (uint32_t)stage * 32768u;
#pragma unroll
    for (int i = 0; i < 4; i++) {
        int idx = tid + i * 256, row = idx >> 3, seg = idx & 7;
        uint32_t sw = swz((uint32_t)(row * 128 + seg * 16));
        cp16(base + sw,          A + (size_t)(m0 + row) * DM_ + kt*64 + seg*8);
        cp16(base + 16384 + sw,  W + (size_t)(o0 + row) * DM_ + kt*64 + seg*8);
    }
}

__device__ __forceinline__ void hmma_mainloop(const __half* __restrict__ A,
                                              const __half* __restrict__ W,
                                              char* smem, int m0, int o0,
                                              float acc[4][4][4]) {
    const int tid = threadIdx.x;
    const int lane = tid & 31, wid = tid >> 5;
    const int wm = wid >> 2, wn = wid & 3;
    const uint32_t sb = smem_u32(smem);

    gemm_load_stage(A, W, sb, m0, o0, 0, 0, tid); CP_COMMIT();
    gemm_load_stage(A, W, sb, m0, o0, 1, 1, tid); CP_COMMIT();

    for (int kt = 0; kt < 8; kt++) {
        CP_WAIT1();
        __syncthreads();
        const uint32_t abase = sb + (uint32_t)(kt % 3) * 32768u;
        const uint32_t bbase = abase + 16384;
#pragma unroll
        for (int ks = 0; ks < 4; ks++) {
            uint32_t af[4][4];
#pragma unroll
            for (int mt = 0; mt < 4; mt++)
                ldm_x4(af[mt], abase + swz((uint32_t)((wm*64 + mt*16 + (lane & 15)) * 128
                                                      + ks*32 + ((lane >> 4) & 1) * 16)));
#pragma unroll
            for (int np = 0; np < 2; np++) {
                uint32_t bf[4];
                ldm_x4(bf, bbase + swz((uint32_t)((wn*32 + np*16 + (lane & 7) + ((lane >> 4) & 1)*8) * 128
                                                  + ks*32 + ((lane >> 3) & 1) * 16)));
#pragma unroll
                for (int mt = 0; mt < 4; mt++) {
                    mma16816(acc[mt][np*2],     af[mt], bf);
                    mma16816(acc[mt][np*2 + 1], af[mt], bf + 2);
                }
            }
        }
        if (kt < 6) gemm_load_stage(A, W, sb, m0, o0, kt + 2, (kt + 2) % 3, tid);
        CP_COMMIT();
    }
}

__global__ __launch_bounds__(256, 2)
void qkv_gemm(const float* __restrict__ bq, const float* __restrict__ bk, const float* __restrict__ bv) {
    extern __shared__ char smem[];
    const int z = blockIdx.z;
    const __half* W = (z == 0) ? g_Wq16 : ((z == 1) ? g_Wk16 : g_Wv16);
    const float* bias = (z == 0) ? bq : ((z == 1) ? bk : bv);
    __half* OUT = (z == 0) ? g_Q16 : ((z == 1) ? g_K16 : g_V16);
    const float scale = (z == 0) ? 0.125f : 1.0f;
    const int m0 = blockIdx.y * 128, o0 = blockIdx.x * 128;

    float acc[4][4][4] = {};
    hmma_mainloop(g_h16, W, smem, m0, o0, acc);

    const int lane = threadIdx.x & 31, wid = threadIdx.x >> 5;
    const int wm = wid >> 2, wn = wid & 3;
    const int g = lane >> 2, t2 = (lane & 3) * 2;
#pragma unroll
    for (int mt = 0; mt < 4; mt++) {
#pragma unroll
        for (int nt = 0; nt < 4; nt++) {
            int o = o0 + wn*32 + nt*8 + t2;
            int hd = o >> 6, dk0 = o & 63;
            float b0 = bias[o], b1 = bias[o + 1];
#pragma unroll
            for (int half = 0; half < 2; half++) {
                int m = m0 + wm*64 + mt*16 + g + half*8;
                int b2 = m >> 10, n2 = m & 1023;
                float v0 = (acc[mt][nt][half*2]     + b0) * scale;
                float v1 = (acc[mt][nt][half*2 + 1] + b1) * scale;
                __half2 hh = __floats2half2_rn(v0, v1);
                *(__half2*)(OUT + (((size_t)(b2*HH + hd)) * NN + n2) * DK_ + dk0) = hh;
            }
        }
    }
}

__global__ __launch_bounds__(256, 2)
void out_gemm(const float* __restrict__ bo, float* __restrict__ out) {
    extern __shared__ char smem[];
    const int m0 = blockIdx.y * 128, o0 = blockIdx.x * 128;

    float acc[4][4][4] = {};
    hmma_mainloop(g_AO16, g_Wo16, smem, m0, o0, acc);

    const int lane = threadIdx.x & 31, wid = threadIdx.x >> 5;
    const int wm = wid >> 2, wn = wid & 3;
    const int g = lane >> 2, t2 = (lane & 3) * 2;
#pragma unroll
    for (int mt = 0; mt < 4; mt++) {
#pragma unroll
        for (int nt = 0; nt < 4; nt++) {
            int o = o0 + wn*32 + nt*8 + t2;
            float b0 = bo[o], b1 = bo[o + 1];
#pragma unroll
            for (int half = 0; half < 2; half++) {
                int m = m0 + wm*64 + mt*16 + g + half*8;
                float* dst = out + (size_t)m * DM_ + o;
                dst[0] = acc[mt][nt][half*2]     + b0;
                dst[1] = acc[mt][nt][half*2 + 1] + b1;
            }
        }
    }
}

// ---------------- HMMA flash attention (cp.async 2-stage K/V, 2 blk/SM) ----
// smem: Q @0 (16KB); stage s (0/1): K @ 16384+s*32768, V @ +16384. Total 80KB.
#define ASMEM 81920

__device__ __forceinline__ void attn_load_kv(const __half* __restrict__ Kb,
                                             const __half* __restrict__ Vb,
                                             uint32_t sb, int j0, int stage, int tid) {
    const uint32_t kbase = sb + 16384u + (uint32_t)stage * 32768u;
#pragma unroll
    for (int i = 0; i < 4; i++) {
        int idx = tid + i * 256, row = idx >> 3, seg = idx & 7;
        uint32_t sw = swz((uint32_t)(row * 128 + seg * 16));
        cp16(kbase + sw,          Kb + (size_t)(j0 + row) * DK_ + seg * 8);
        cp16(kbase + 16384 + sw,  Vb + (size_t)(j0 + row) * DK_ + seg * 8);
    }
}

__global__ __launch_bounds__(256, 2)
void attn_hmma() {
    extern __shared__ char smem[];
    const uint32_t sb = smem_u32(smem);
    const int tid = threadIdx.x;
    const int lane = tid & 31, w = tid >> 5;
    const int g = lane >> 2, t2 = (lane & 3) * 2;

    const int bh = blockIdx.y;
    const int b2 = bh >> 3, h2 = bh & 7;
    const int i0 = blockIdx.x * 128;
    const int heff = g_uniform ? 0 : h2;

    const __half* Kb = g_K16 + (size_t)bh * NN * DK_;
    const __half* Vb = g_V16 + (size_t)bh * NN * DK_;

    // kick off stage 0 (overlap with Q setup)
    attn_load_kv(Kb, Vb, sb, 0, 0, tid); CP_COMMIT();

    // load Q tile [128][64] swizzled — one 16B segment per store
    const __half* Qg = g_Q16 + ((size_t)bh * NN + i0) * DK_;
#pragma unroll
    for (int i = 0; i < 4; i++) {
        int idx = tid + i * 256, row = idx >> 3, seg = idx & 7;
        uint32_t sw = swz((uint32_t)(row * 128 + seg * 16));
        *(uint4*)(smem + sw) = *(const uint4*)(Qg + (size_t)row * DK_ + seg * 8);
    }
    __syncthreads();

    // Q fragments register-resident: 4 k16 steps
    uint32_t qa[4][4];
#pragma unroll
    for (int ks = 0; ks < 4; ks++)
        ldm_x4(qa[ks], sb + swz((uint32_t)((w*16 + (lane & 15)) * 128
                                           + ks*32 + ((lane >> 4) & 1) * 16)));

    float m1 = -1e30f, m2 = -1e30f, l1 = 0.f, l2 = 0.f;
    float o_[8][4] = {};

    const float* Bg = g_bias + ((size_t)(b2*HH + heff) * NN + i0) * NN;

    for (int jt = 0; jt < 8; jt++) {
        const int j0 = jt * 128;
        CP_WAIT0();
        __syncthreads();
        // issue next stage now — overlaps with this tile's compute
        if (jt < 7) { attn_load_kv(Kb, Vb, sb, (jt + 1) * 128, (jt + 1) & 1, tid); CP_COMMIT(); }

        const uint32_t KOFF = 16384u + (uint32_t)(jt & 1) * 32768u;
        const uint32_t VOFF = KOFF + 16384u;

        // init S accumulators with the geodesic bias (L2 latency hides
        // under the QK MMAs below — mma accumulates in place on top)
        float sf[16][4];
        const float* bp1 = Bg + (size_t)(16*w + g) * NN + j0 + t2;
        const float* bp2 = bp1 + 8 * NN;
#pragma unroll
        for (int nt = 0; nt < 16; nt++) {
            float2 bv1 = *(const float2*)(bp1 + nt*8);
            float2 bv2 = *(const float2*)(bp2 + nt*8);
            sf[nt][0] = bv1.x; sf[nt][1] = bv1.y;
            sf[nt][2] = bv2.x; sf[nt][3] = bv2.y;
        }

        // S = bias + Q @ K^T : 16 n8 tiles
#pragma unroll
        for (int np = 0; np < 8; np++) {
#pragma unroll
            for (int ks = 0; ks < 4; ks++) {
                uint32_t bf[4];
                ldm_x4(bf, sb + KOFF + swz((uint32_t)((np*16 + (lane & 7) + ((lane >> 4) & 1)*8) * 128
                                                      + ks*32 + ((lane >> 3) & 1) * 16)));
                mma16816(sf[np*2],     qa[ks], bf);
                mma16816(sf[np*2 + 1], qa[ks], bf + 2);
            }
        }

        // warp-local online softmax (rows g and g+8 of this warp's slab)
        float mx1 = sf[0][0], mx2 = sf[0][2];
#pragma unroll
        for (int nt = 0; nt < 16; nt++) {
            mx1 = fmaxf(mx1, fmaxf(sf[nt][0], sf[nt][1]));
            mx2 = fmaxf(mx2, fmaxf(sf[nt][2], sf[nt][3]));
        }
        mx1 = fmaxf(mx1, __shfl_xor_sync(0xffffffffu, mx1, 1));
        mx1 = fmaxf(mx1, __shfl_xor_sync(0xffffffffu, mx1, 2));
        mx2 = fmaxf(mx2, __shfl_xor_sync(0xffffffffu, mx2, 1));
        mx2 = fmaxf(mx2, __shfl_xor_sync(0xffffffffu, mx2, 2));

        float n1 = fmaxf(m1, mx1), n2 = fmaxf(m2, mx2);
        float f1 = __expf(m1 - n1), f2 = __expf(m2 - n2);
        float rs1 = 0.f, rs2 = 0.f;
#pragma unroll
        for (int nt = 0; nt < 16; nt++) {
            sf[nt][0] = __expf(sf[nt][0] - n1);
            sf[nt][1] = __expf(sf[nt][1] - n1);
            sf[nt][2] = __expf(sf[nt][2] - n2);
            sf[nt][3] = __expf(sf[nt][3] - n2);
            rs1 += sf[nt][0] + sf[nt][1];
            rs2 += sf[nt][2] + sf[nt][3];
        }
        rs1 += __shfl_xor_sync(0xffffffffu, rs1, 1);
        rs1 += __shfl_xor_sync(0xffffffffu, rs1, 2);
        rs2 += __shfl_xor_sync(0xffffffffu, rs2, 1);
        rs2 += __shfl_xor_sync(0xffffffffu, rs2, 2);
        l1 = l1 * f1 + rs1;  m1 = n1;
        l2 = l2 * f2 + rs2;  m2 = n2;

#pragma unroll
        for (int dt = 0; dt < 8; dt++) {
            o_[dt][0] *= f1; o_[dt][1] *= f1;
            o_[dt][2] *= f2; o_[dt][3] *= f2;
        }

        // O += P @ V : k over j (8 k16 chunks), n over d (8 n8 tiles)
#pragma unroll
        for (int kk = 0; kk < 8; kk++) {
            uint32_t pa[4];
            {
                __half2 h0 = __floats2half2_rn(sf[2*kk][0],   sf[2*kk][1]);
                __half2 h1 = __floats2half2_rn(sf[2*kk][2],   sf[2*kk][3]);
                __half2 h2_ = __floats2half2_rn(sf[2*kk+1][0], sf[2*kk+1][1]);
                __half2 h3 = __floats2half2_rn(sf[2*kk+1][2], sf[2*kk+1][3]);
                pa[0] = *(uint32_t*)&h0; pa[1] = *(uint32_t*)&h1;
                pa[2] = *(uint32_t*)&h2_; pa[3] = *(uint32_t*)&h3;
            }
#pragma unroll
            for (int dp = 0; dp < 4; dp++) {
                uint32_t bf[4];
                ldm_x4_t(bf, sb + VOFF + swz((uint32_t)((kk*16 + (lane & 7) + ((lane >> 3) & 1)*8) * 128
                                                        + dp*32 + ((lane >> 4) & 1) * 16)));
                mma16816(o_[dp*2],     pa, bf);
                mma16816(o_[dp*2 + 1], pa, bf + 2);
            }
        }
    }

    // epilogue
    float i1 = 1.0f / l1, i2 = 1.0f / l2;
    __half* dst1 = g_AO16 + ((size_t)b2 * NN + i0 + 16*w + g)     * DM_ + h2*DK_ + t2;
    __half* dst2 = g_AO16 + ((size_t)b2 * NN + i0 + 16*w + g + 8) * DM_ + h2*DK_ + t2;
#pragma unroll
    for (int dt = 0; dt < 8; dt++) {
        *(__half2*)(dst1 + dt*8) = __floats2half2_rn(o_[dt][0] * i1, o_[dt][1] * i1);
        *(__half2*)(dst2 + dt*8) = __floats2half2_rn(o_[dt][2] * i2, o_[dt][3] * i2);
    }
}

// ---------------- launcher ----------------
extern "C" void kernel_launch(void* const* d_in, const int* in_sizes, int n_in,
                              void* d_out, int out_size) {
    const float* h    = (const float*)d_in[0];
    const float* x    = (const float*)d_in[1];
    const float* Wq   = (const float*)d_in[2];
    const float* bq   = (const float*)d_in[3];
    const float* Wk   = (const float*)d_in[4];
    const float* bk   = (const float*)d_in[5];
    const float* Wv   = (const float*)d_in[6];
    const float* bv   = (const float*)d_in[7];
    const float* Wo   = (const float*)d_in[8];
    const float* bo   = (const float*)d_in[9];
    const float* alpha= (const float*)d_in[10];
    const float* lsig = (const float*)d_in[11];
    float* out = (float*)d_out;

    // lazily-created side stream + fork/join events (host objects only;
    // identical work every call, graph-capture-legal fork pattern)
    static cudaStream_t s2 = nullptr;
    static cudaEvent_t evFork = nullptr, evJoin = nullptr;
    if (s2 == nullptr) {
        cudaStreamCreateWithFlags(&s2, cudaStreamNonBlocking);
        cudaEventCreateWithFlags(&evFork, cudaEventDisableTiming);
        cudaEventCreateWithFlags(&evJoin, cudaEventDisableTiming);
    }

    cudaFuncSetAttribute(qkv_gemm, cudaFuncAttributeMaxDynamicSharedMemorySize, GSMEM);
    cudaFuncSetAttribute(out_gemm, cudaFuncAttributeMaxDynamicSharedMemorySize, GSMEM);
    cudaFuncSetAttribute(attn_hmma, cudaFuncAttributeMaxDynamicSharedMemorySize, ASMEM);

    // main stream: coef/sq prep (bias deps), then fork
    prep_coef_kernel<<<1, 32>>>(alpha, lsig);
    sq_kernel<<<(BB*NN*CC + 127)/128, 128>>>(x);
    cudaEventRecord(evFork, 0);
    cudaStreamWaitEvent(s2, evFork, 0);

    // side stream: bias matrix — overlaps convert + qkv on main stream
    bias_kernel<<<dim3(NN/64, NN/64, BB*HH), 256, 0, s2>>>(x);
    cudaEventRecord(evJoin, s2);

    // main stream: convert + QKV projections
    convert_kernel<<<(BB*NN*DM_ + 255)/256, 256>>>(h, Wq, Wk, Wv, Wo);
    qkv_gemm<<<dim3(DM_/128, (BB*NN)/128, 3), 256, GSMEM>>>(bq, bk, bv);

    // join: attention needs both qkv (main) and bias (side)
    cudaStreamWaitEvent(0, evJoin, 0);
    attn_hmma<<<dim3(NN/128, BB*HH), 256, ASMEM>>>();

    out_gemm<<<dim3(DM_/128, (BB*NN)/128), 256, GSMEM>>>(bo, out);
}

// round 12
// speedup vs baseline: 5.3296x; 1.0193x over previous
#include <cuda_runtime.h>
#include <cuda_fp16.h>
#include <math.h>
#include <stdint.h>

#define BB  4
#define NN  1024
#define DM_ 512
#define HH  8
#define CC  3
#define DC_ 16
#define DK_ 64
#define XW  (CC*DC_)

// ---------------- device scratch (16B-aligned for vector ld/st) ------------
__device__ __align__(16) __half g_h16[(size_t)BB*NN*DM_];
__device__ __align__(16) __half g_Wq16[DM_*DM_];
__device__ __align__(16) __half g_Wk16[DM_*DM_];
__device__ __align__(16) __half g_Wv16[DM_*DM_];
__device__ __align__(16) __half g_Wo16[DM_*DM_];
__device__ __align__(16) __half g_Q16[(size_t)BB*HH*NN*DK_];
__device__ __align__(16) __half g_K16[(size_t)BB*HH*NN*DK_];
__device__ __align__(16) __half g_V16[(size_t)BB*HH*NN*DK_];
__device__ __align__(16) __half g_AO16[(size_t)BB*NN*DM_];
__device__ __align__(16) float  g_bias[(size_t)BB*HH*NN*NN];
__device__ __align__(16) float  g_sq[BB*NN*CC];
__device__ __align__(16) float  g_alpha[HH*CC];
__device__ __align__(16) float  g_gcoef[HH*CC];
__device__ int    g_uniform;

// ---------------- helpers ----------------
__device__ __forceinline__ uint32_t smem_u32(const void* p) {
    uint32_t a;
    asm("{ .reg .u64 t; cvta.to.shared.u64 t, %1; cvt.u32.u64 %0, t; }" : "=r"(a) : "l"(p));
    return a;
}
__device__ __forceinline__ uint32_t swz(uint32_t o) { return o ^ ((o >> 3) & 0x70); }

__device__ __forceinline__ void mma16816(float* d, const uint32_t* a, const uint32_t* b) {
    asm volatile("mma.sync.aligned.m16n8k16.row.col.f32.f16.f16.f32 "
        "{%0,%1,%2,%3}, {%4,%5,%6,%7}, {%8,%9}, {%0,%1,%2,%3};"
        : "+f"(d[0]), "+f"(d[1]), "+f"(d[2]), "+f"(d[3])
        : "r"(a[0]), "r"(a[1]), "r"(a[2]), "r"(a[3]), "r"(b[0]), "r"(b[1]));
}
__device__ __forceinline__ void ldm_x4(uint32_t* r, uint32_t addr) {
    asm volatile("ldmatrix.sync.aligned.m8n8.x4.shared.b16 {%0,%1,%2,%3}, [%4];"
        : "=r"(r[0]), "=r"(r[1]), "=r"(r[2]), "=r"(r[3]) : "r"(addr));
}
__device__ __forceinline__ void ldm_x4_t(uint32_t* r, uint32_t addr) {
    asm volatile("ldmatrix.sync.aligned.m8n8.x4.trans.shared.b16 {%0,%1,%2,%3}, [%4];"
        : "=r"(r[0]), "=r"(r[1]), "=r"(r[2]), "=r"(r[3]) : "r"(addr));
}
__device__ __forceinline__ void cp16(uint32_t saddr, const void* gptr) {
    asm volatile("cp.async.cg.shared.global [%0], [%1], 16;" :: "r"(saddr), "l"(gptr));
}
#define CP_COMMIT() asm volatile("cp.async.commit_group;" ::: "memory")
#define CP_WAIT1()  asm volatile("cp.async.wait_group 1;" ::: "memory")
#define CP_WAIT0()  asm volatile("cp.async.wait_group 0;" ::: "memory")

// ---------------- small prep kernels ----------------
__global__ void prep_coef_kernel(const float* __restrict__ alpha, const float* __restrict__ lsig) {
    int i = threadIdx.x;   // 32 threads, HH*CC = 24 live
    int ok = 1;
    if (i < HH*CC) {
        float a = alpha[i], l = lsig[i];
        float s = expf(l);
        if (s < 1e-4f) s = 1e-4f;
        g_gcoef[i] = 1.0f / (2.0f * s * s);
        g_alpha[i] = a;
        ok = (a == alpha[i % CC]) && (l == lsig[i % CC]);
    }
    int uni = __all_sync(0xffffffffu, ok);
    if (i == 0) g_uniform = uni;
}

__global__ void sq_kernel(const float* __restrict__ x) {
    int t = blockIdx.x * blockDim.x + threadIdx.x;
    if (t >= BB*NN*CC) return;
    int c = t % CC; int bn = t / CC;
    const float* p = x + (size_t)bn * XW + c * DC_;
    float s = 0.f;
#pragma unroll
    for (int d = 0; d < DC_; d++) s += p[d] * p[d];
    g_sq[t] = s;
}

// vectorized fp32 -> fp16 conversion: 8 elements per thread
__device__ __forceinline__ void cvt8(const float* __restrict__ src, __half* __restrict__ dst) {
    float4 a = *(const float4*)src;
    float4 b = *(const float4*)(src + 4);
    __half2 r[4];
    r[0] = __floats2half2_rn(a.x, a.y);
    r[1] = __floats2half2_rn(a.z, a.w);
    r[2] = __floats2half2_rn(b.x, b.y);
    r[3] = __floats2half2_rn(b.z, b.w);
    *(uint4*)dst = *(uint4*)r;
}

__global__ void convert_kernel(const float* __restrict__ h,
                               const float* __restrict__ wq, const float* __restrict__ wk,
                               const float* __restrict__ wv, const float* __restrict__ wo) {
    int i = blockIdx.x * blockDim.x + threadIdx.x;
    if (i < BB*NN*DM_/8) cvt8(h + (size_t)i*8, g_h16 + (size_t)i*8);
    if (i < DM_*DM_/8) {
        cvt8(wq + i*8, g_Wq16 + i*8);
        cvt8(wk + i*8, g_Wk16 + i*8);
        cvt8(wv + i*8, g_Wv16 + i*8);
        cvt8(wo + i*8, g_Wo16 + i*8);
    }
}

// ---------------- geodesic bias (fp32) ----------------
__global__ __launch_bounds__(256)
void bias_kernel(const float* __restrict__ x) {
    __shared__ float Xi[64][49];
    __shared__ float Xj[64][49];
    __shared__ float sqi[64][3];
    __shared__ float sqj[64][3];

    const int bh = blockIdx.z;
    const int h2 = bh & (HH-1);
    const int b2 = bh >> 3;
    if (g_uniform && h2 > 0) return;

    const int i0 = blockIdx.y * 64, j0 = blockIdx.x * 64;
    const int tid = threadIdx.x;
    const int tx = tid & 15, ty = tid >> 4;

    const float* xb = x + (size_t)b2 * NN * XW;
#pragma unroll
    for (int t = 0; t < 12; t++) {
        int idx = tid + t * 256;
        int row = idx / XW, col = idx % XW;
        Xi[row][col] = xb[(size_t)(i0 + row) * XW + col];
        Xj[row][col] = xb[(size_t)(j0 + row) * XW + col];
    }
    if (tid < 192) {
        int row = tid / 3, c = tid % 3;
        sqi[row][c] = g_sq[((size_t)b2 * NN + i0 + row) * CC + c];
        sqj[row][c] = g_sq[((size_t)b2 * NN + j0 + row) * CC + c];
    }
    __syncthreads();

    float Acf[CC], Gcf[CC];
#pragma unroll
    for (int c = 0; c < CC; c++) { Acf[c] = g_alpha[h2*CC + c]; Gcf[c] = g_gcoef[h2*CC + c]; }

    float* outp = g_bias + (size_t)(b2*HH + h2) * NN * NN;

#pragma unroll
    for (int r = 0; r < 4; r++) {
        int i = 4*ty + r;
        float4 res;
        float* resp = (float*)&res;
#pragma unroll
        for (int c = 0; c < 4; c++) {
            int j = 4*tx + c;
            float bsum = 0.f;
#pragma unroll
            for (int cm = 0; cm < CC; cm++) {
                float inner = 0.f;
#pragma unroll
                for (int d = 0; d < DC_; d++)
                    inner = fmaf(Xi[i][cm*DC_ + d], Xj[j][cm*DC_ + d], inner);
                float dd = fmaxf(sqi[i][cm] + sqj[j][cm] - 2.f * inner, 0.f);
                bsum = fmaf(Acf[cm], __expf(-dd * Gcf[cm]), bsum);
            }
            resp[c] = bsum;
        }
        *(float4*)(outp + (size_t)(i0 + i) * NN + j0 + 4*tx) = res;
    }
}

// ---------------- HMMA GEMM (128x128 block, K=512, cp.async 3-stage) -------
// stage s: A tile @ s*32768, B tile @ s*32768 + 16384; 3 stages = 96KB
#define GSMEM 98304

__device__ __forceinline__ void gemm_load_stage(const __half* __restrict__ A,
                                                const __half* __restrict__ W,
                                                uint32_t sb, int m0, int o0,
                                                int kt, int stage, int tid) {
    const uint32_t base = sb + (uint32_t)stage * 32768u;
#pragma unroll
    for (int i = 0; i < 4; i++) {
        int idx = tid + i * 256, row = idx >> 3, seg = idx & 7;
        uint32_t sw = swz((uint32_t)(row * 128 + seg * 16));
        cp16(base + sw,          A + (size_t)(m0 + row) * DM_ + kt*64 + seg*8);
        cp16(base + 16384 + sw,  W + (size_t)(o0 + row) * DM_ + kt*64 + seg*8);
    }
}

__device__ __forceinline__ void hmma_mainloop(const __half* __restrict__ A,
                                              const __half* __restrict__ W,
                                              char* smem, int m0, int o0,
                                              float acc[4][4][4]) {
    const int tid = threadIdx.x;
    const int lane = tid & 31, wid = tid >> 5;
    const int wm = wid >> 2, wn = wid & 3;
    const uint32_t sb = smem_u32(smem);

    gemm_load_stage(A, W, sb, m0, o0, 0, 0, tid); CP_COMMIT();
    gemm_load_stage(A, W, sb, m0, o0, 1, 1, tid); CP_COMMIT();

    for (int kt = 0; kt < 8; kt++) {
        CP_WAIT1();
        __syncthreads();
        const uint32_t abase = sb + (uint32_t)(kt % 3) * 32768u;
        const uint32_t bbase = abase + 16384;
#pragma unroll
        for (int ks = 0; ks < 4; ks++) {
            uint32_t af[4][4];
#pragma unroll
            for (int mt = 0; mt < 4; mt++)
                ldm_x4(af[mt], abase + swz((uint32_t)((wm*64 + mt*16 + (lane & 15)) * 128
                                                      + ks*32 + ((lane >> 4) & 1) * 16)));
#pragma unroll
            for (int np = 0; np < 2; np++) {
                uint32_t bf[4];
                ldm_x4(bf, bbase + swz((uint32_t)((wn*32 + np*16 + (lane & 7) + ((lane >> 4) & 1)*8) * 128
                                                  + ks*32 + ((lane >> 3) & 1) * 16)));
#pragma unroll
                for (int mt = 0; mt < 4; mt++) {
                    mma16816(acc[mt][np*2],     af[mt], bf);
                    mma16816(acc[mt][np*2 + 1], af[mt], bf + 2);
                }
            }
        }
        if (kt < 6) gemm_load_stage(A, W, sb, m0, o0, kt + 2, (kt + 2) % 3, tid);
        CP_COMMIT();
    }
}

__global__ __launch_bounds__(256, 2)
void qkv_gemm(const float* __restrict__ bq, const float* __restrict__ bk, const float* __restrict__ bv) {
    extern __shared__ char smem[];
    const int z = blockIdx.z;
    const __half* W = (z == 0) ? g_Wq16 : ((z == 1) ? g_Wk16 : g_Wv16);
    const float* bias = (z == 0) ? bq : ((z == 1) ? bk : bv);
    __half* OUT = (z == 0) ? g_Q16 : ((z == 1) ? g_K16 : g_V16);
    const float scale = (z == 0) ? 0.125f : 1.0f;
    const int m0 = blockIdx.y * 128, o0 = blockIdx.x * 128;

    float acc[4][4][4] = {};
    hmma_mainloop(g_h16, W, smem, m0, o0, acc);

    const int lane = threadIdx.x & 31, wid = threadIdx.x >> 5;
    const int wm = wid >> 2, wn = wid & 3;
    const int g = lane >> 2, t2 = (lane & 3) * 2;
#pragma unroll
    for (int mt = 0; mt < 4; mt++) {
#pragma unroll
        for (int nt = 0; nt < 4; nt++) {
            int o = o0 + wn*32 + nt*8 + t2;
            int hd = o >> 6, dk0 = o & 63;
            float b0 = bias[o], b1 = bias[o + 1];
#pragma unroll
            for (int half = 0; half < 2; half++) {
                int m = m0 + wm*64 + mt*16 + g + half*8;
                int b2 = m >> 10, n2 = m & 1023;
                float v0 = (acc[mt][nt][half*2]     + b0) * scale;
                float v1 = (acc[mt][nt][half*2 + 1] + b1) * scale;
                __half2 hh = __floats2half2_rn(v0, v1);
                *(__half2*)(OUT + (((size_t)(b2*HH + hd)) * NN + n2) * DK_ + dk0) = hh;
            }
        }
    }
}

__global__ __launch_bounds__(256, 2)
void out_gemm(const float* __restrict__ bo, float* __restrict__ out) {
    extern __shared__ char smem[];
    const int m0 = blockIdx.y * 128, o0 = blockIdx.x * 128;

    float acc[4][4][4] = {};
    hmma_mainloop(g_AO16, g_Wo16, smem, m0, o0, acc);

    const int lane = threadIdx.x & 31, wid = threadIdx.x >> 5;
    const int wm = wid >> 2, wn = wid & 3;
    const int g = lane >> 2, t2 = (lane & 3) * 2;
#pragma unroll
    for (int mt = 0; mt < 4; mt++) {
#pragma unroll
        for (int nt = 0; nt < 4; nt++) {
            int o = o0 + wn*32 + nt*8 + t2;
            float b0 = bo[o], b1 = bo[o + 1];
#pragma unroll
            for (int half = 0; half < 2; half++) {
                int m = m0 + wm*64 + mt*16 + g + half*8;
                float* dst = out + (size_t)m * DM_ + o;
                dst[0] = acc[mt][nt][half*2]     + b0;
                dst[1] = acc[mt][nt][half*2 + 1] + b1;
            }
        }
    }
}

// ---------------- HMMA flash attention (cp.async 2-stage K/V, 2 blk/SM) ----
// smem: Q @0 (16KB); stage s (0/1): K @ 16384+s*32768, V @ +16384. Total 80KB.
#define ASMEM 81920

__device__ __forceinline__ void attn_load_kv(const __half* __restrict__ Kb,
                                             const __half* __restrict__ Vb,
                                             uint32_t sb, int j0, int stage, int tid) {
    const uint32_t kbase = sb + 16384u + (uint32_t)stage * 32768u;
#pragma unroll
    for (int i = 0; i < 4; i++) {
        int idx = tid + i * 256, row = idx >> 3, seg = idx & 7;
        uint32_t sw = swz((uint32_t)(row * 128 + seg * 16));
        cp16(kbase + sw,          Kb + (size_t)(j0 + row) * DK_ + seg * 8);
        cp16(kbase + 16384 + sw,  Vb + (size_t)(j0 + row) * DK_ + seg * 8);
    }
}

__global__ __launch_bounds__(256, 2)
void attn_hmma() {
    extern __shared__ char smem[];
    const uint32_t sb = smem_u32(smem);
    const int tid = threadIdx.x;
    const int lane = tid & 31, w = tid >> 5;
    const int g = lane >> 2, t2 = (lane & 3) * 2;

    const int bh = blockIdx.y;
    const int b2 = bh >> 3, h2 = bh & 7;
    const int i0 = blockIdx.x * 128;
    const int heff = g_uniform ? 0 : h2;

    const __half* Kb = g_K16 + (size_t)bh * NN * DK_;
    const __half* Vb = g_V16 + (size_t)bh * NN * DK_;

    // kick off stage 0 (overlap with Q setup)
    attn_load_kv(Kb, Vb, sb, 0, 0, tid); CP_COMMIT();

    // load Q tile [128][64] swizzled — one 16B segment per store
    const __half* Qg = g_Q16 + ((size_t)bh * NN + i0) * DK_;
#pragma unroll
    for (int i = 0; i < 4; i++) {
        int idx = tid + i * 256, row = idx >> 3, seg = idx & 7;
        uint32_t sw = swz((uint32_t)(row * 128 + seg * 16));
        *(uint4*)(smem + sw) = *(const uint4*)(Qg + (size_t)row * DK_ + seg * 8);
    }
    __syncthreads();

    // Q fragments register-resident: 4 k16 steps
    uint32_t qa[4][4];
#pragma unroll
    for (int ks = 0; ks < 4; ks++)
        ldm_x4(qa[ks], sb + swz((uint32_t)((w*16 + (lane & 15)) * 128
                                           + ks*32 + ((lane >> 4) & 1) * 16)));

    float m1 = -1e30f, m2 = -1e30f, l1 = 0.f, l2 = 0.f;
    float o_[8][4] = {};

    const float* Bg = g_bias + ((size_t)(b2*HH + heff) * NN + i0) * NN;

    for (int jt = 0; jt < 8; jt++) {
        const int j0 = jt * 128;
        CP_WAIT0();
        __syncthreads();
        // issue next stage now — overlaps with this tile's compute
        if (jt < 7) { attn_load_kv(Kb, Vb, sb, (jt + 1) * 128, (jt + 1) & 1, tid); CP_COMMIT(); }

        const uint32_t KOFF = 16384u + (uint32_t)(jt & 1) * 32768u;
        const uint32_t VOFF = KOFF + 16384u;

        // init S accumulators with the geodesic bias (L2 latency hides
        // under the QK MMAs below — mma accumulates in place on top)
        float sf[16][4];
        const float* bp1 = Bg + (size_t)(16*w + g) * NN + j0 + t2;
        const float* bp2 = bp1 + 8 * NN;
#pragma unroll
        for (int nt = 0; nt < 16; nt++) {
            float2 bv1 = *(const float2*)(bp1 + nt*8);
            float2 bv2 = *(const float2*)(bp2 + nt*8);
            sf[nt][0] = bv1.x; sf[nt][1] = bv1.y;
            sf[nt][2] = bv2.x; sf[nt][3] = bv2.y;
        }

        // S = bias + Q @ K^T : 16 n8 tiles
#pragma unroll
        for (int np = 0; np < 8; np++) {
#pragma unroll
            for (int ks = 0; ks < 4; ks++) {
                uint32_t bf[4];
                ldm_x4(bf, sb + KOFF + swz((uint32_t)((np*16 + (lane & 7) + ((lane >> 4) & 1)*8) * 128
                                                      + ks*32 + ((lane >> 3) & 1) * 16)));
                mma16816(sf[np*2],     qa[ks], bf);
                mma16816(sf[np*2 + 1], qa[ks], bf + 2);
            }
        }

        // warp-local online softmax (rows g and g+8 of this warp's slab)
        float mx1 = sf[0][0], mx2 = sf[0][2];
#pragma unroll
        for (int nt = 0; nt < 16; nt++) {
            mx1 = fmaxf(mx1, fmaxf(sf[nt][0], sf[nt][1]));
            mx2 = fmaxf(mx2, fmaxf(sf[nt][2], sf[nt][3]));
        }
        mx1 = fmaxf(mx1, __shfl_xor_sync(0xffffffffu, mx1, 1));
        mx1 = fmaxf(mx1, __shfl_xor_sync(0xffffffffu, mx1, 2));
        mx2 = fmaxf(mx2, __shfl_xor_sync(0xffffffffu, mx2, 1));
        mx2 = fmaxf(mx2, __shfl_xor_sync(0xffffffffu, mx2, 2));

        float n1 = fmaxf(m1, mx1), n2 = fmaxf(m2, mx2);
        float f1 = __expf(m1 - n1), f2 = __expf(m2 - n2);
        float rs1 = 0.f, rs2 = 0.f;
#pragma unroll
        for (int nt = 0; nt < 16; nt++) {
            sf[nt][0] = __expf(sf[nt][0] - n1);
            sf[nt][1] = __expf(sf[nt][1] - n1);
            sf[nt][2] = __expf(sf[nt][2] - n2);
            sf[nt][3] = __expf(sf[nt][3] - n2);
            rs1 += sf[nt][0] + sf[nt][1];
            rs2 += sf[nt][2] + sf[nt][3];
        }
        rs1 += __shfl_xor_sync(0xffffffffu, rs1, 1);
        rs1 += __shfl_xor_sync(0xffffffffu, rs1, 2);
        rs2 += __shfl_xor_sync(0xffffffffu, rs2, 1);
        rs2 += __shfl_xor_sync(0xffffffffu, rs2, 2);
        l1 = l1 * f1 + rs1;  m1 = n1;
        l2 = l2 * f2 + rs2;  m2 = n2;

#pragma unroll
        for (int dt = 0; dt < 8; dt++) {
            o_[dt][0] *= f1; o_[dt][1] *= f1;
            o_[dt][2] *= f2; o_[dt][3] *= f2;
        }

        // O += P @ V : k over j (8 k16 chunks), n over d (8 n8 tiles)
#pragma unroll
        for (int kk = 0; kk < 8; kk++) {
            uint32_t pa[4];
            {
                __half2 h0 = __floats2half2_rn(sf[2*kk][0],   sf[2*kk][1]);
                __half2 h1 = __floats2half2_rn(sf[2*kk][2],   sf[2*kk][3]);
                __half2 h2_ = __floats2half2_rn(sf[2*kk+1][0], sf[2*kk+1][1]);
                __half2 h3 = __floats2half2_rn(sf[2*kk+1][2], sf[2*kk+1][3]);
                pa[0] = *(uint32_t*)&h0; pa[1] = *(uint32_t*)&h1;
                pa[2] = *(uint32_t*)&h2_; pa[3] = *(uint32_t*)&h3;
            }
#pragma unroll
            for (int dp = 0; dp < 4; dp++) {
                uint32_t bf[4];
                ldm_x4_t(bf, sb + VOFF + swz((uint32_t)((kk*16 + (lane & 7) + ((lane >> 3) & 1)*8) * 128
                                                        + dp*32 + ((lane >> 4) & 1) * 16)));
                mma16816(o_[dp*2],     pa, bf);
                mma16816(o_[dp*2 + 1], pa, bf + 2);
            }
        }
    }

    // epilogue
    float i1 = 1.0f / l1, i2 = 1.0f / l2;
    __half* dst1 = g_AO16 + ((size_t)b2 * NN + i0 + 16*w + g)     * DM_ + h2*DK_ + t2;
    __half* dst2 = g_AO16 + ((size_t)b2 * NN + i0 + 16*w + g + 8) * DM_ + h2*DK_ + t2;
#pragma unroll
    for (int dt = 0; dt < 8; dt++) {
        *(__half2*)(dst1 + dt*8) = __floats2half2_rn(o_[dt][0] * i1, o_[dt][1] * i1);
        *(__half2*)(dst2 + dt*8) = __floats2half2_rn(o_[dt][2] * i2, o_[dt][3] * i2);
    }
}

// ---------------- launcher ----------------
extern "C" void kernel_launch(void* const* d_in, const int* in_sizes, int n_in,
                              void* d_out, int out_size) {
    const float* h    = (const float*)d_in[0];
    const float* x    = (const float*)d_in[1];
    const float* Wq   = (const float*)d_in[2];
    const float* bq   = (const float*)d_in[3];
    const float* Wk   = (const float*)d_in[4];
    const float* bk   = (const float*)d_in[5];
    const float* Wv   = (const float*)d_in[6];
    const float* bv   = (const float*)d_in[7];
    const float* Wo   = (const float*)d_in[8];
    const float* bo   = (const float*)d_in[9];
    const float* alpha= (const float*)d_in[10];
    const float* lsig = (const float*)d_in[11];
    float* out = (float*)d_out;

    // lazily-created side stream + fork/join events (host objects only;
    // identical work every call, graph-capture-legal fork pattern)
    static cudaStream_t s2 = nullptr;
    static cudaEvent_t evFork = nullptr, evJoin = nullptr;
    if (s2 == nullptr) {
        cudaStreamCreateWithFlags(&s2, cudaStreamNonBlocking);
        cudaEventCreateWithFlags(&evFork, cudaEventDisableTiming);
        cudaEventCreateWithFlags(&evJoin, cudaEventDisableTiming);
    }

    cudaFuncSetAttribute(qkv_gemm, cudaFuncAttributeMaxDynamicSharedMemorySize, GSMEM);
    cudaFuncSetAttribute(out_gemm, cudaFuncAttributeMaxDynamicSharedMemorySize, GSMEM);
    cudaFuncSetAttribute(attn_hmma, cudaFuncAttributeMaxDynamicSharedMemorySize, ASMEM);

    // fork immediately: side stream owns the whole bias chain
    cudaEventRecord(evFork, 0);
    cudaStreamWaitEvent(s2, evFork, 0);
    prep_coef_kernel<<<1, 32, 0, s2>>>(alpha, lsig);
    sq_kernel<<<(BB*NN*CC + 127)/128, 128, 0, s2>>>(x);
    bias_kernel<<<dim3(NN/64, NN/64, BB*HH), 256, 0, s2>>>(x);
    cudaEventRecord(evJoin, s2);

    // main stream: convert + QKV projections (critical path)
    convert_kernel<<<(BB*NN*DM_/8 + 255)/256, 256>>>(h, Wq, Wk, Wv, Wo);
    qkv_gemm<<<dim3(DM_/128, (BB*NN)/128, 3), 256, GSMEM>>>(bq, bk, bv);

    // join: attention needs qkv (main) + bias/uniform-flag (side)
    cudaStreamWaitEvent(0, evJoin, 0);
    attn_hmma<<<dim3(NN/128, BB*HH), 256, ASMEM>>>();

    out_gemm<<<dim3(DM_/128, (BB*NN)/128), 256, GSMEM>>>(bo, out);
}

// round 13
// speedup vs baseline: 5.4061x; 1.0144x over previous
#include <cuda_runtime.h>
#include <cuda_fp16.h>
#include <math.h>
#include <stdint.h>

#define BB  4
#define NN  1024
#define DM_ 512
#define HH  8
#define CC  3
#define DC_ 16
#define DK_ 64
#define XW  (CC*DC_)
#define LOG2E 1.44269504088896340736f

// ---------------- device scratch (16B-aligned for vector ld/st) ------------
__device__ __align__(16) __half g_h16[(size_t)BB*NN*DM_];
__device__ __align__(16) __half g_Wq16[DM_*DM_];
__device__ __align__(16) __half g_Wk16[DM_*DM_];
__device__ __align__(16) __half g_Wv16[DM_*DM_];
__device__ __align__(16) __half g_Wo16[DM_*DM_];
__device__ __align__(16) __half g_Q16[(size_t)BB*HH*NN*DK_];
__device__ __align__(16) __half g_K16[(size_t)BB*HH*NN*DK_];
__device__ __align__(16) __half g_V16[(size_t)BB*HH*NN*DK_];
__device__ __align__(16) __half g_AO16[(size_t)BB*NN*DM_];
__device__ __align__(16) float  g_bias[(size_t)BB*HH*NN*NN];   // stores bias * log2(e)
__device__ __align__(16) float  g_sq[BB*NN*CC];
__device__ __align__(16) float  g_alpha[HH*CC];
__device__ __align__(16) float  g_gcoef[HH*CC];
__device__ int    g_uniform;

// ---------------- helpers ----------------
__device__ __forceinline__ uint32_t smem_u32(const void* p) {
    uint32_t a;
    asm("{ .reg .u64 t; cvta.to.shared.u64 t, %1; cvt.u32.u64 %0, t; }" : "=r"(a) : "l"(p));
    return a;
}
__device__ __forceinline__ uint32_t swz(uint32_t o) { return o ^ ((o >> 3) & 0x70); }

__device__ __forceinline__ void mma16816(float* d, const uint32_t* a, const uint32_t* b) {
    asm volatile("mma.sync.aligned.m16n8k16.row.col.f32.f16.f16.f32 "
        "{%0,%1,%2,%3}, {%4,%5,%6,%7}, {%8,%9}, {%0,%1,%2,%3};"
        : "+f"(d[0]), "+f"(d[1]), "+f"(d[2]), "+f"(d[3])
        : "r"(a[0]), "r"(a[1]), "r"(a[2]), "r"(a[3]), "r"(b[0]), "r"(b[1]));
}
__device__ __forceinline__ void ldm_x4(uint32_t* r, uint32_t addr) {
    asm volatile("ldmatrix.sync.aligned.m8n8.x4.shared.b16 {%0,%1,%2,%3}, [%4];"
        : "=r"(r[0]), "=r"(r[1]), "=r"(r[2]), "=r"(r[3]) : "r"(addr));
}
__device__ __forceinline__ void ldm_x4_t(uint32_t* r, uint32_t addr) {
    asm volatile("ldmatrix.sync.aligned.m8n8.x4.trans.shared.b16 {%0,%1,%2,%3}, [%4];"
        : "=r"(r[0]), "=r"(r[1]), "=r"(r[2]), "=r"(r[3]) : "r"(addr));
}
__device__ __forceinline__ void cp16(uint32_t saddr, const void* gptr) {
    asm volatile("cp.async.cg.shared.global [%0], [%1], 16;" :: "r"(saddr), "l"(gptr));
}
#define CP_COMMIT() asm volatile("cp.async.commit_group;" ::: "memory")
#define CP_WAIT1()  asm volatile("cp.async.wait_group 1;" ::: "memory")
#define CP_WAIT0()  asm volatile("cp.async.wait_group 0;" ::: "memory")

// ---------------- small prep kernels ----------------
__global__ void prep_coef_kernel(const float* __restrict__ alpha, const float* __restrict__ lsig) {
    int i = threadIdx.x;   // 32 threads, HH*CC = 24 live
    int ok = 1;
    if (i < HH*CC) {
        float a = alpha[i], l = lsig[i];
        float s = expf(l);
        if (s < 1e-4f) s = 1e-4f;
        g_gcoef[i] = 1.0f / (2.0f * s * s);
        g_alpha[i] = a;
        ok = (a == alpha[i % CC]) && (l == lsig[i % CC]);
    }
    int uni = __all_sync(0xffffffffu, ok);
    if (i == 0) g_uniform = uni;
}

__global__ void sq_kernel(const float* __restrict__ x) {
    int t = blockIdx.x * blockDim.x + threadIdx.x;
    if (t >= BB*NN*CC) return;
    int c = t % CC; int bn = t / CC;
    const float* p = x + (size_t)bn * XW + c * DC_;
    float s = 0.f;
#pragma unroll
    for (int d = 0; d < DC_; d++) s += p[d] * p[d];
    g_sq[t] = s;
}

// vectorized fp32 -> fp16 conversion: 8 elements per step
__device__ __forceinline__ void cvt8(const float* __restrict__ src, __half* __restrict__ dst) {
    float4 a = *(const float4*)src;
    float4 b = *(const float4*)(src + 4);
    __half2 r[4];
    r[0] = __floats2half2_rn(a.x, a.y);
    r[1] = __floats2half2_rn(a.z, a.w);
    r[2] = __floats2half2_rn(b.x, b.y);
    r[3] = __floats2half2_rn(b.z, b.w);
    *(uint4*)dst = *(uint4*)r;
}

__global__ void convert_kernel(const float* __restrict__ h,
                               const float* __restrict__ wq, const float* __restrict__ wk,
                               const float* __restrict__ wv, const float* __restrict__ wo) {
    int i = blockIdx.x * blockDim.x + threadIdx.x;
    if (i < BB*NN*DM_/16) {
        cvt8(h + (size_t)i*16,     g_h16 + (size_t)i*16);
        cvt8(h + (size_t)i*16 + 8, g_h16 + (size_t)i*16 + 8);
    }
    if (i < DM_*DM_/16) {
        cvt8(wq + i*16, g_Wq16 + i*16); cvt8(wq + i*16 + 8, g_Wq16 + i*16 + 8);
        cvt8(wk + i*16, g_Wk16 + i*16); cvt8(wk + i*16 + 8, g_Wk16 + i*16 + 8);
        cvt8(wv + i*16, g_Wv16 + i*16); cvt8(wv + i*16 + 8, g_Wv16 + i*16 + 8);
        cvt8(wo + i*16, g_Wo16 + i*16); cvt8(wo + i*16 + 8, g_Wo16 + i*16 + 8);
    }
}

// ---------------- geodesic bias (fp32; output scaled by log2e) -------------
__global__ __launch_bounds__(256)
void bias_kernel(const float* __restrict__ x) {
    __shared__ float Xi[64][49];
    __shared__ float Xj[64][49];
    __shared__ float sqi[64][3];
    __shared__ float sqj[64][3];

    const int bh = blockIdx.z;
    const int h2 = bh & (HH-1);
    const int b2 = bh >> 3;
    if (g_uniform && h2 > 0) return;

    const int i0 = blockIdx.y * 64, j0 = blockIdx.x * 64;
    const int tid = threadIdx.x;
    const int tx = tid & 15, ty = tid >> 4;

    const float* xb = x + (size_t)b2 * NN * XW;
#pragma unroll
    for (int t = 0; t < 12; t++) {
        int idx = tid + t * 256;
        int row = idx / XW, col = idx % XW;
        Xi[row][col] = xb[(size_t)(i0 + row) * XW + col];
        Xj[row][col] = xb[(size_t)(j0 + row) * XW + col];
    }
    if (tid < 192) {
        int row = tid / 3, c = tid % 3;
        sqi[row][c] = g_sq[((size_t)b2 * NN + i0 + row) * CC + c];
        sqj[row][c] = g_sq[((size_t)b2 * NN + j0 + row) * CC + c];
    }
    __syncthreads();

    float Acf[CC], Gcf[CC];
#pragma unroll
    for (int c = 0; c < CC; c++) {
        Acf[c] = g_alpha[h2*CC + c] * LOG2E;   // fold log2e for base-2 softmax
        Gcf[c] = g_gcoef[h2*CC + c];
    }

    float* outp = g_bias + (size_t)(b2*HH + h2) * NN * NN;

#pragma unroll
    for (int r = 0; r < 4; r++) {
        int i = 4*ty + r;
        float4 res;
        float* resp = (float*)&res;
#pragma unroll
        for (int c = 0; c < 4; c++) {
            int j = 4*tx + c;
            float bsum = 0.f;
#pragma unroll
            for (int cm = 0; cm < CC; cm++) {
                float inner = 0.f;
#pragma unroll
                for (int d = 0; d < DC_; d++)
                    inner = fmaf(Xi[i][cm*DC_ + d], Xj[j][cm*DC_ + d], inner);
                float dd = fmaxf(sqi[i][cm] + sqj[j][cm] - 2.f * inner, 0.f);
                bsum = fmaf(Acf[cm], __expf(-dd * Gcf[cm]), bsum);
            }
            resp[c] = bsum;
        }
        *(float4*)(outp + (size_t)(i0 + i) * NN + j0 + 4*tx) = res;
    }
}

// ---------------- HMMA GEMM (128x128 block, K=512, cp.async 3-stage) -------
#define GSMEM 98304

__device__ __forceinline__ void gemm_load_stage(const __half* __restrict__ A,
                                                const __half* __restrict__ W,
                                                uint32_t sb, int m0, int o0,
                                                int kt, int stage, int tid) {
    const uint32_t base = sb + (uint32_t)stage * 32768u;
#pragma unroll
    for (int i = 0; i < 4; i++) {
        int idx = tid + i * 256, row = idx >> 3, seg = idx & 7;
        uint32_t sw = swz((uint32_t)(row * 128 + seg * 16));
        cp16(base + sw,          A + (size_t)(m0 + row) * DM_ + kt*64 + seg*8);
        cp16(base + 16384 + sw,  W + (size_t)(o0 + row) * DM_ + kt*64 + seg*8);
    }
}

__device__ __forceinline__ void hmma_mainloop(const __half* __restrict__ A,
                                              const __half* __restrict__ W,
                                              char* smem, int m0, int o0,
                                              float acc[4][4][4]) {
    const int tid = threadIdx.x;
    const int lane = tid & 31, wid = tid >> 5;
    const int wm = wid >> 2, wn = wid & 3;
    const uint32_t sb = smem_u32(smem);

    gemm_load_stage(A, W, sb, m0, o0, 0, 0, tid); CP_COMMIT();
    gemm_load_stage(A, W, sb, m0, o0, 1, 1, tid); CP_COMMIT();

    for (int kt = 0; kt < 8; kt++) {
        CP_WAIT1();
        __syncthreads();
        const uint32_t abase = sb + (uint32_t)(kt % 3) * 32768u;
        const uint32_t bbase = abase + 16384;
#pragma unroll
        for (int ks = 0; ks < 4; ks++) {
            uint32_t af[4][4];
#pragma unroll
            for (int mt = 0; mt < 4; mt++)
                ldm_x4(af[mt], abase + swz((uint32_t)((wm*64 + mt*16 + (lane & 15)) * 128
                                                      + ks*32 + ((lane >> 4) & 1) * 16)));
#pragma unroll
            for (int np = 0; np < 2; np++) {
                uint32_t bf[4];
                ldm_x4(bf, bbase + swz((uint32_t)((wn*32 + np*16 + (lane & 7) + ((lane >> 4) & 1)*8) * 128
                                                  + ks*32 + ((lane >> 3) & 1) * 16)));
#pragma unroll
                for (int mt = 0; mt < 4; mt++) {
                    mma16816(acc[mt][np*2],     af[mt], bf);
                    mma16816(acc[mt][np*2 + 1], af[mt], bf + 2);
                }
            }
        }
        if (kt < 6) gemm_load_stage(A, W, sb, m0, o0, kt + 2, (kt + 2) % 3, tid);
        CP_COMMIT();
    }
}

__global__ __launch_bounds__(256, 2)
void qkv_gemm(const float* __restrict__ bq, const float* __restrict__ bk, const float* __restrict__ bv) {
    extern __shared__ char smem[];
    const int z = blockIdx.z;
    const __half* W = (z == 0) ? g_Wq16 : ((z == 1) ? g_Wk16 : g_Wv16);
    const float* bias = (z == 0) ? bq : ((z == 1) ? bk : bv);
    __half* OUT = (z == 0) ? g_Q16 : ((z == 1) ? g_K16 : g_V16);
    // Q gets 1/sqrt(dk) * log2(e) folded in (base-2 softmax)
    const float scale = (z == 0) ? (0.125f * LOG2E) : 1.0f;
    const int m0 = blockIdx.y * 128, o0 = blockIdx.x * 128;

    float acc[4][4][4] = {};
    hmma_mainloop(g_h16, W, smem, m0, o0, acc);

    const int lane = threadIdx.x & 31, wid = threadIdx.x >> 5;
    const int wm = wid >> 2, wn = wid & 3;
    const int g = lane >> 2, t2 = (lane & 3) * 2;
#pragma unroll
    for (int mt = 0; mt < 4; mt++) {
#pragma unroll
        for (int nt = 0; nt < 4; nt++) {
            int o = o0 + wn*32 + nt*8 + t2;
            int hd = o >> 6, dk0 = o & 63;
            float b0 = bias[o], b1 = bias[o + 1];
#pragma unroll
            for (int half = 0; half < 2; half++) {
                int m = m0 + wm*64 + mt*16 + g + half*8;
                int b2 = m >> 10, n2 = m & 1023;
                float v0 = (acc[mt][nt][half*2]     + b0) * scale;
                float v1 = (acc[mt][nt][half*2 + 1] + b1) * scale;
                __half2 hh = __floats2half2_rn(v0, v1);
                *(__half2*)(OUT + (((size_t)(b2*HH + hd)) * NN + n2) * DK_ + dk0) = hh;
            }
        }
    }
}

__global__ __launch_bounds__(256, 2)
void out_gemm(const float* __restrict__ bo, float* __restrict__ out) {
    extern __shared__ char smem[];
    const int m0 = blockIdx.y * 128, o0 = blockIdx.x * 128;

    float acc[4][4][4] = {};
    hmma_mainloop(g_AO16, g_Wo16, smem, m0, o0, acc);

    const int lane = threadIdx.x & 31, wid = threadIdx.x >> 5;
    const int wm = wid >> 2, wn = wid & 3;
    const int g = lane >> 2, t2 = (lane & 3) * 2;
#pragma unroll
    for (int mt = 0; mt < 4; mt++) {
#pragma unroll
        for (int nt = 0; nt < 4; nt++) {
            int o = o0 + wn*32 + nt*8 + t2;
            float b0 = bo[o], b1 = bo[o + 1];
#pragma unroll
            for (int half = 0; half < 2; half++) {
                int m = m0 + wm*64 + mt*16 + g + half*8;
                float* dst = out + (size_t)m * DM_ + o;
                dst[0] = acc[mt][nt][half*2]     + b0;
                dst[1] = acc[mt][nt][half*2 + 1] + b1;
            }
        }
    }
}

// ---------------- HMMA flash attention (cp.async 2-stage K/V, 2 blk/SM) ----
#define ASMEM 81920

__device__ __forceinline__ void attn_load_kv(const __half* __restrict__ Kb,
                                             const __half* __restrict__ Vb,
                                             uint32_t sb, int j0, int stage, int tid) {
    const uint32_t kbase = sb + 16384u + (uint32_t)stage * 32768u;
#pragma unroll
    for (int i = 0; i < 4; i++) {
        int idx = tid + i * 256, row = idx >> 3, seg = idx & 7;
        uint32_t sw = swz((uint32_t)(row * 128 + seg * 16));
        cp16(kbase + sw,          Kb + (size_t)(j0 + row) * DK_ + seg * 8);
        cp16(kbase + 16384 + sw,  Vb + (size_t)(j0 + row) * DK_ + seg * 8);
    }
}

__global__ __launch_bounds__(256, 2)
void attn_hmma() {
    extern __shared__ char smem[];
    const uint32_t sb = smem_u32(smem);
    const int tid = threadIdx.x;
    const int lane = tid & 31, w = tid >> 5;
    const int g = lane >> 2, t2 = (lane & 3) * 2;

    const int bh = blockIdx.y;
    const int b2 = bh >> 3, h2 = bh & 7;
    const int i0 = blockIdx.x * 128;
    const int heff = g_uniform ? 0 : h2;

    const __half* Kb = g_K16 + (size_t)bh * NN * DK_;
    const __half* Vb = g_V16 + (size_t)bh * NN * DK_;

    attn_load_kv(Kb, Vb, sb, 0, 0, tid); CP_COMMIT();

    const __half* Qg = g_Q16 + ((size_t)bh * NN + i0) * DK_;
#pragma unroll
    for (int i = 0; i < 4; i++) {
        int idx = tid + i * 256, row = idx >> 3, seg = idx & 7;
        uint32_t sw = swz((uint32_t)(row * 128 + seg * 16));
        *(uint4*)(smem + sw) = *(const uint4*)(Qg + (size_t)row * DK_ + seg * 8);
    }
    __syncthreads();

    uint32_t qa[4][4];
#pragma unroll
    for (int ks = 0; ks < 4; ks++)
        ldm_x4(qa[ks], sb + swz((uint32_t)((w*16 + (lane & 15)) * 128
                                           + ks*32 + ((lane >> 4) & 1) * 16)));

    float m1 = -1e30f, m2 = -1e30f, l1 = 0.f, l2 = 0.f;
    float o_[8][4] = {};

    const float* Bg = g_bias + ((size_t)(b2*HH + heff) * NN + i0) * NN;

    for (int jt = 0; jt < 8; jt++) {
        const int j0 = jt * 128;
        CP_WAIT0();
        __syncthreads();
        if (jt < 7) { attn_load_kv(Kb, Vb, sb, (jt + 1) * 128, (jt + 1) & 1, tid); CP_COMMIT(); }

        const uint32_t KOFF = 16384u + (uint32_t)(jt & 1) * 32768u;
        const uint32_t VOFF = KOFF + 16384u;

        // init S accumulators with the geodesic bias (already in log2 units)
        float sf[16][4];
        const float* bp1 = Bg + (size_t)(16*w + g) * NN + j0 + t2;
        const float* bp2 = bp1 + 8 * NN;
#pragma unroll
        for (int nt = 0; nt < 16; nt++) {
            float2 bv1 = *(const float2*)(bp1 + nt*8);
            float2 bv2 = *(const float2*)(bp2 + nt*8);
            sf[nt][0] = bv1.x; sf[nt][1] = bv1.y;
            sf[nt][2] = bv2.x; sf[nt][3] = bv2.y;
        }

        // S = bias + Q @ K^T  (logits in base-2 units)
#pragma unroll
        for (int np = 0; np < 8; np++) {
#pragma unroll
            for (int ks = 0; ks < 4; ks++) {
                uint32_t bf[4];
                ldm_x4(bf, sb + KOFF + swz((uint32_t)((np*16 + (lane & 7) + ((lane >> 4) & 1)*8) * 128
                                                      + ks*32 + ((lane >> 3) & 1) * 16)));
                mma16816(sf[np*2],     qa[ks], bf);
                mma16816(sf[np*2 + 1], qa[ks], bf + 2);
            }
        }

        // row max (warp-local, rows g and g+8)
        float mx1 = sf[0][0], mx2 = sf[0][2];
#pragma unroll
        for (int nt = 0; nt < 16; nt++) {
            mx1 = fmaxf(mx1, fmaxf(sf[nt][0], sf[nt][1]));
            mx2 = fmaxf(mx2, fmaxf(sf[nt][2], sf[nt][3]));
        }
        mx1 = fmaxf(mx1, __shfl_xor_sync(0xffffffffu, mx1, 1));
        mx1 = fmaxf(mx1, __shfl_xor_sync(0xffffffffu, mx1, 2));
        mx2 = fmaxf(mx2, __shfl_xor_sync(0xffffffffu, mx2, 1));
        mx2 = fmaxf(mx2, __shfl_xor_sync(0xffffffffu, mx2, 2));

        float n1 = fmaxf(m1, mx1), n2 = fmaxf(m2, mx2);
        float f1 = exp2f(m1 - n1), f2 = exp2f(m2 - n2);
        m1 = n1; m2 = n2;

        // rescale O before accumulating this tile
#pragma unroll
        for (int dt = 0; dt < 8; dt++) {
            o_[dt][0] *= f1; o_[dt][1] *= f1;
            o_[dt][2] *= f2; o_[dt][3] *= f2;
        }

        // exp (MUFU) interleaved with PV MMA (tensor) per k16 chunk:
        // chunk kk's exps issue while chunk kk-1's HMMAs are in flight.
        float rs1 = 0.f, rs2 = 0.f;
#pragma unroll
        for (int kk = 0; kk < 8; kk++) {
            float e00 = exp2f(sf[2*kk][0]   - n1), e01 = exp2f(sf[2*kk][1]   - n1);
            float e02 = exp2f(sf[2*kk][2]   - n2), e03 = exp2f(sf[2*kk][3]   - n2);
            float e10 = exp2f(sf[2*kk+1][0] - n1), e11 = exp2f(sf[2*kk+1][1] - n1);
            float e12 = exp2f(sf[2*kk+1][2] - n2), e13 = exp2f(sf[2*kk+1][3] - n2);
            rs1 += e00 + e01 + e10 + e11;
            rs2 += e02 + e03 + e12 + e13;

            uint32_t pa[4];
            {
                __half2 h0 = __floats2half2_rn(e00, e01);
                __half2 h1 = __floats2half2_rn(e02, e03);
                __half2 h2_ = __floats2half2_rn(e10, e11);
                __half2 h3 = __floats2half2_rn(e12, e13);
                pa[0] = *(uint32_t*)&h0; pa[1] = *(uint32_t*)&h1;
                pa[2] = *(uint32_t*)&h2_; pa[3] = *(uint32_t*)&h3;
            }
#pragma unroll
            for (int dp = 0; dp < 4; dp++) {
                uint32_t bf[4];
                ldm_x4_t(bf, sb + VOFF + swz((uint32_t)((kk*16 + (lane & 7) + ((lane >> 3) & 1)*8) * 128
                                                        + dp*32 + ((lane >> 4) & 1) * 16)));
                mma16816(o_[dp*2],     pa, bf);
                mma16816(o_[dp*2 + 1], pa, bf + 2);
            }
        }

        // row-sum reduction after PV (off the critical MUFU->tensor path)
        rs1 += __shfl_xor_sync(0xffffffffu, rs1, 1);
        rs1 += __shfl_xor_sync(0xffffffffu, rs1, 2);
        rs2 += __shfl_xor_sync(0xffffffffu, rs2, 1);
        rs2 += __shfl_xor_sync(0xffffffffu, rs2, 2);
        l1 = l1 * f1 + rs1;
        l2 = l2 * f2 + rs2;
    }

    // epilogue
    float i1 = 1.0f / l1, i2 = 1.0f / l2;
    __half* dst1 = g_AO16 + ((size_t)b2 * NN + i0 + 16*w + g)     * DM_ + h2*DK_ + t2;
    __half* dst2 = g_AO16 + ((size_t)b2 * NN + i0 + 16*w + g + 8) * DM_ + h2*DK_ + t2;
#pragma unroll
    for (int dt = 0; dt < 8; dt++) {
        *(__half2*)(dst1 + dt*8) = __floats2half2_rn(o_[dt][0] * i1, o_[dt][1] * i1);
        *(__half2*)(dst2 + dt*8) = __floats2half2_rn(o_[dt][2] * i2, o_[dt][3] * i2);
    }
}

// ---------------- launcher ----------------
extern "C" void kernel_launch(void* const* d_in, const int* in_sizes, int n_in,
                              void* d_out, int out_size) {
    const float* h    = (const float*)d_in[0];
    const float* x    = (const float*)d_in[1];
    const float* Wq   = (const float*)d_in[2];
    const float* bq   = (const float*)d_in[3];
    const float* Wk   = (const float*)d_in[4];
    const float* bk   = (const float*)d_in[5];
    const float* Wv   = (const float*)d_in[6];
    const float* bv   = (const float*)d_in[7];
    const float* Wo   = (const float*)d_in[8];
    const float* bo   = (const float*)d_in[9];
    const float* alpha= (const float*)d_in[10];
    const float* lsig = (const float*)d_in[11];
    float* out = (float*)d_out;

    static cudaStream_t s2 = nullptr;
    static cudaEvent_t evFork = nullptr, evJoin = nullptr;
    if (s2 == nullptr) {
        cudaStreamCreateWithFlags(&s2, cudaStreamNonBlocking);
        cudaEventCreateWithFlags(&evFork, cudaEventDisableTiming);
        cudaEventCreateWithFlags(&evJoin, cudaEventDisableTiming);
    }

    cudaFuncSetAttribute(qkv_gemm, cudaFuncAttributeMaxDynamicSharedMemorySize, GSMEM);
    cudaFuncSetAttribute(out_gemm, cudaFuncAttributeMaxDynamicSharedMemorySize, GSMEM);
    cudaFuncSetAttribute(attn_hmma, cudaFuncAttributeMaxDynamicSharedMemorySize, ASMEM);

    // fork: side stream owns the whole bias chain
    cudaEventRecord(evFork, 0);
    cudaStreamWaitEvent(s2, evFork, 0);
    prep_coef_kernel<<<1, 32, 0, s2>>>(alpha, lsig);
    sq_kernel<<<(BB*NN*CC + 127)/128, 128, 0, s2>>>(x);
    bias_kernel<<<dim3(NN/64, NN/64, BB*HH), 256, 0, s2>>>(x);
    cudaEventRecord(evJoin, s2);

    // main stream: convert + QKV projections (critical path)
    convert_kernel<<<(BB*NN*DM_/16 + 255)/256, 256>>>(h, Wq, Wk, Wv, Wo);
    qkv_gemm<<<dim3(DM_/128, (BB*NN)/128, 3), 256, GSMEM>>>(bq, bk, bv);

    cudaStreamWaitEvent(0, evJoin, 0);
    attn_hmma<<<dim3(NN/128, BB*HH), 256, ASMEM>>>();

    out_gemm<<<dim3(DM_/128, (BB*NN)/128), 256, GSMEM>>>(bo, out);
}